// round 1
// baseline (speedup 1.0000x reference)
#include <cuda_runtime.h>
#include <math.h>

// ---------------------------------------------------------------------------
// GCN2: 3 layers, each layer = two GCNConv branches (edge set 1 & 2) + ELU +
// learned per-channel softmax combine.
// Dims: 512 -> 1024 -> 512 -> 128, N = 10000 nodes.
// ---------------------------------------------------------------------------

#define NN 10000        // nodes
#define CMAX 1024       // max channel count

// Scratch (static device allocations; no cudaMalloc allowed)
__device__ float g_lin1[NN * CMAX];
__device__ float g_lin2[NN * CMAX];
__device__ float g_agg1[NN * CMAX];
__device__ float g_agg2[NN * CMAX];
__device__ float g_h   [NN * CMAX];
__device__ float g_deg1[NN];
__device__ float g_deg2[NN];
__device__ float g_dinv1[NN];
__device__ float g_dinv2[NN];

// ---------------------------------------------------------------------------
// Degree kernels
// ---------------------------------------------------------------------------
__global__ void zero_deg_kernel(float* deg1, float* deg2, int n) {
    int i = blockIdx.x * blockDim.x + threadIdx.x;
    if (i < n) { deg1[i] = 0.f; deg2[i] = 0.f; }
}

__global__ void count_deg_kernel(const int* __restrict__ dst, float* deg, int E) {
    int e = blockIdx.x * blockDim.x + threadIdx.x;
    if (e < E) atomicAdd(&deg[dst[e]], 1.0f);
}

__global__ void dinv_kernel(const float* __restrict__ deg1, const float* __restrict__ deg2,
                            float* dinv1, float* dinv2, int n) {
    int i = blockIdx.x * blockDim.x + threadIdx.x;
    if (i < n) {
        dinv1[i] = rsqrtf(deg1[i] + 1.0f);   // +1 self-loop, always >= 1
        dinv2[i] = rsqrtf(deg2[i] + 1.0f);
    }
}

// ---------------------------------------------------------------------------
// Tiled fp32 GEMM:  C[M,N] = A[M,K] @ B[K,N]
// BM=BN=64, BK=16, 256 threads, 4x4 per-thread microtile, float4 loads.
// Requires: N % 64 == 0, K % 16 == 0 (true for all layers). M unrestricted.
// ---------------------------------------------------------------------------
#define BM 64
#define BN 64
#define BK 16

__global__ __launch_bounds__(256) void gemm_kernel(
    const float* __restrict__ A, const float* __restrict__ B,
    float* __restrict__ C, int M, int N, int K)
{
    __shared__ float As[BK][BM];       // transposed A tile
    __shared__ float Bs[BK][BN];

    int tid = threadIdx.x;
    int block_row = blockIdx.y * BM;
    int block_col = blockIdx.x * BN;

    // A load: thread -> (row = tid/4, 4 cols at (tid%4)*4)
    int row_a = tid >> 2;
    int col_a = (tid & 3) * 4;
    // B load: thread -> (row = tid/16, 4 cols at (tid%16)*4)
    int row_b = tid >> 4;
    int col_b = (tid & 15) * 4;

    int ty = tid >> 4;    // 0..15  -> rows ty*4..ty*4+3
    int tx = tid & 15;    // 0..15  -> cols tx*4..tx*4+3

    float acc[4][4] = {};

    for (int k0 = 0; k0 < K; k0 += BK) {
        int ga = block_row + row_a;
        float4 av;
        if (ga < M) av = *(const float4*)(A + (size_t)ga * K + k0 + col_a);
        else        av = make_float4(0.f, 0.f, 0.f, 0.f);
        As[col_a + 0][row_a] = av.x;
        As[col_a + 1][row_a] = av.y;
        As[col_a + 2][row_a] = av.z;
        As[col_a + 3][row_a] = av.w;

        float4 bv = *(const float4*)(B + (size_t)(k0 + row_b) * N + block_col + col_b);
        *(float4*)&Bs[row_b][col_b] = bv;

        __syncthreads();

        #pragma unroll
        for (int k = 0; k < BK; k++) {
            float4 a4 = *(const float4*)&As[k][ty * 4];
            float4 b4 = *(const float4*)&Bs[k][tx * 4];
            float am[4] = {a4.x, a4.y, a4.z, a4.w};
            float bn[4] = {b4.x, b4.y, b4.z, b4.w};
            #pragma unroll
            for (int i = 0; i < 4; i++)
                #pragma unroll
                for (int j = 0; j < 4; j++)
                    acc[i][j] += am[i] * bn[j];
        }
        __syncthreads();
    }

    #pragma unroll
    for (int i = 0; i < 4; i++) {
        int gr = block_row + ty * 4 + i;
        if (gr < M) {
            float4 o = make_float4(acc[i][0], acc[i][1], acc[i][2], acc[i][3]);
            *(float4*)(C + (size_t)gr * N + block_col + tx * 4) = o;
        }
    }
}

// ---------------------------------------------------------------------------
// Self-loop init: agg[i,c] = lin[i,c] * dinv[i]^2   (also resets the buffer)
// ---------------------------------------------------------------------------
__global__ void selfloop_kernel(const float* __restrict__ lin,
                                const float* __restrict__ dinv,
                                float* __restrict__ agg, int n, int C)
{
    int idx = blockIdx.x * blockDim.x + threadIdx.x;   // over n * C/4
    int total = n * (C >> 2);
    if (idx >= total) return;
    int row = idx / (C >> 2);
    float w = dinv[row]; w = w * w;
    float4 v = ((const float4*)lin)[idx];
    v.x *= w; v.y *= w; v.z *= w; v.w *= w;
    ((float4*)agg)[idx] = v;
}

// ---------------------------------------------------------------------------
// Edge scatter: one warp per edge.  agg[d,:] += lin[s,:] * dinv[s]*dinv[d]
// ---------------------------------------------------------------------------
__global__ void scatter_kernel(const float* __restrict__ lin,
                               const float* __restrict__ dinv,
                               const int* __restrict__ src,
                               const int* __restrict__ dst,
                               float* __restrict__ agg, int E, int C)
{
    int gwarp = (blockIdx.x * blockDim.x + threadIdx.x) >> 5;
    int lane = threadIdx.x & 31;
    if (gwarp >= E) return;
    int s = src[gwarp];
    int d = dst[gwarp];
    float coef = dinv[s] * dinv[d];
    const float4* srow = (const float4*)(lin + (size_t)s * C);
    float* drow = agg + (size_t)d * C;
    int c4n = C >> 2;
    for (int c4 = lane; c4 < c4n; c4 += 32) {
        float4 v = srow[c4];
        atomicAdd(drow + 4 * c4 + 0, v.x * coef);
        atomicAdd(drow + 4 * c4 + 1, v.y * coef);
        atomicAdd(drow + 4 * c4 + 2, v.z * coef);
        atomicAdd(drow + 4 * c4 + 3, v.w * coef);
    }
}

// ---------------------------------------------------------------------------
// Combine: out[i,c] = elu(agg1+b1)*w0(c) + elu(agg2+b2)*(1-w0(c))
// w0(c) = softmax(aw[c,:])[0] = 1/(1+exp(aw[c,1]-aw[c,0]))
// ---------------------------------------------------------------------------
__device__ __forceinline__ float elu1(float x) {
    return x > 0.f ? x : expm1f(x);
}

__global__ void combine_kernel(const float* __restrict__ agg1, const float* __restrict__ b1,
                               const float* __restrict__ agg2, const float* __restrict__ b2,
                               const float* __restrict__ aw,
                               float* __restrict__ out, int n, int C)
{
    int idx = blockIdx.x * blockDim.x + threadIdx.x;
    if (idx >= n * C) return;
    int c = idx % C;
    float w0 = 1.0f / (1.0f + expf(aw[2 * c + 1] - aw[2 * c]));
    float v1 = elu1(agg1[idx] + b1[c]);
    float v2 = elu1(agg2[idx] + b2[c]);
    out[idx] = v1 * w0 + v2 * (1.0f - w0);
}

// ---------------------------------------------------------------------------
// Host side
// ---------------------------------------------------------------------------
static void run_layer(const float* x, int n, int Cin, int Cout,
                      const float* Wa, const float* ba,
                      const float* Wb, const float* bb,
                      const float* aw,
                      const int* src1, const int* dst1, int E1,
                      const int* src2, const int* dst2, int E2,
                      float* lin1, float* lin2, float* agg1, float* agg2,
                      float* dinv1, float* dinv2,
                      float* out)
{
    dim3 gg(Cout / BN, (n + BM - 1) / BM);
    gemm_kernel<<<gg, 256>>>(x, Wa, lin1, n, Cout, Cin);
    gemm_kernel<<<gg, 256>>>(x, Wb, lin2, n, Cout, Cin);

    int tot4 = n * (Cout >> 2);
    selfloop_kernel<<<(tot4 + 255) / 256, 256>>>(lin1, dinv1, agg1, n, Cout);
    selfloop_kernel<<<(tot4 + 255) / 256, 256>>>(lin2, dinv2, agg2, n, Cout);

    scatter_kernel<<<(E1 + 7) / 8, 256>>>(lin1, dinv1, src1, dst1, agg1, E1, Cout);
    scatter_kernel<<<(E2 + 7) / 8, 256>>>(lin2, dinv2, src2, dst2, agg2, E2, Cout);

    int tot = n * Cout;
    combine_kernel<<<(tot + 255) / 256, 256>>>(agg1, ba, agg2, bb, aw, out, n, Cout);
}

extern "C" void kernel_launch(void* const* d_in, const int* in_sizes, int n_in,
                              void* d_out, int out_size)
{
    const float* x   = (const float*)d_in[0];
    const int*   ei1 = (const int*)d_in[1];
    const int*   ei2 = (const int*)d_in[2];
    const float* W11 = (const float*)d_in[3];  const float* b11 = (const float*)d_in[4];
    const float* W12 = (const float*)d_in[5];  const float* b12 = (const float*)d_in[6];
    const float* W21 = (const float*)d_in[7];  const float* b21 = (const float*)d_in[8];
    const float* W22 = (const float*)d_in[9];  const float* b22 = (const float*)d_in[10];
    const float* W31 = (const float*)d_in[11]; const float* b31 = (const float*)d_in[12];
    const float* W32 = (const float*)d_in[13]; const float* b32 = (const float*)d_in[14];
    const float* aw1 = (const float*)d_in[15];
    const float* aw2 = (const float*)d_in[16];
    const float* aw3 = (const float*)d_in[17];

    int n  = in_sizes[0] / 512;
    int E1 = in_sizes[1] / 2;
    int E2 = in_sizes[2] / 2;

    const int* src1 = ei1;
    const int* dst1 = ei1 + E1;
    const int* src2 = ei2;
    const int* dst2 = ei2 + E2;

    float *lin1, *lin2, *agg1, *agg2, *h, *deg1, *deg2, *dinv1, *dinv2;
    cudaGetSymbolAddress((void**)&lin1,  g_lin1);
    cudaGetSymbolAddress((void**)&lin2,  g_lin2);
    cudaGetSymbolAddress((void**)&agg1,  g_agg1);
    cudaGetSymbolAddress((void**)&agg2,  g_agg2);
    cudaGetSymbolAddress((void**)&h,     g_h);
    cudaGetSymbolAddress((void**)&deg1,  g_deg1);
    cudaGetSymbolAddress((void**)&deg2,  g_deg2);
    cudaGetSymbolAddress((void**)&dinv1, g_dinv1);
    cudaGetSymbolAddress((void**)&dinv2, g_dinv2);

    // Degrees (with self-loop +1 folded into dinv_kernel)
    zero_deg_kernel<<<(n + 255) / 256, 256>>>(deg1, deg2, n);
    count_deg_kernel<<<(E1 + 255) / 256, 256>>>(dst1, deg1, E1);
    count_deg_kernel<<<(E2 + 255) / 256, 256>>>(dst2, deg2, E2);
    dinv_kernel<<<(n + 255) / 256, 256>>>(deg1, deg2, dinv1, dinv2, n);

    // Layer 1: 512 -> 1024
    run_layer(x, n, 512, 1024, W11, b11, W12, b12, aw1,
              src1, dst1, E1, src2, dst2, E2,
              lin1, lin2, agg1, agg2, dinv1, dinv2, h);

    // Layer 2: 1024 -> 512
    run_layer(h, n, 1024, 512, W21, b21, W22, b22, aw2,
              src1, dst1, E1, src2, dst2, E2,
              lin1, lin2, agg1, agg2, dinv1, dinv2, h);

    // Layer 3: 512 -> 128 -> d_out
    run_layer(h, n, 512, 128, W31, b31, W32, b32, aw3,
              src1, dst1, E1, src2, dst2, E2,
              lin1, lin2, agg1, agg2, dinv1, dinv2, (float*)d_out);
}

// round 3
// speedup vs baseline: 1.3466x; 1.3466x over previous
#include <cuda_runtime.h>
#include <cuda_bf16.h>
#include <cstdint>
#include <math.h>

// ===========================================================================
// GCN2 on GB300 (portable-ISA tensor path): ldmatrix + mma.sync bf16 GEMMs
// with 3-term split (hh+hl+lh) for fp32-like accuracy, + atomic scatter agg.
// Layers: 512 -> 1024 -> 512 -> 128, N = 10000 nodes, two edge sets.
// NOTE: tcgen05 is NOT available (harness PTX targets compute_103, not 103a).
// ===========================================================================

#define NN 10000
#define CMAX 1024

__device__ float g_lin1[NN * CMAX];
__device__ float g_lin2[NN * CMAX];
__device__ float g_agg1[NN * CMAX];
__device__ float g_agg2[NN * CMAX];
__device__ float g_h   [NN * CMAX];
__device__ float g_deg1[NN];
__device__ float g_deg2[NN];
__device__ float g_dinv1[NN];
__device__ float g_dinv2[NN];
__device__ __nv_bfloat16 g_xh[NN * CMAX];
__device__ __nv_bfloat16 g_xl[NN * CMAX];
__device__ __nv_bfloat16 g_wth1[1024 * 1024];
__device__ __nv_bfloat16 g_wtl1[1024 * 1024];
__device__ __nv_bfloat16 g_wth2[1024 * 1024];
__device__ __nv_bfloat16 g_wtl2[1024 * 1024];

// ---------------------------------------------------------------------------
__device__ __forceinline__ uint32_t smem_u32(const void* p) {
    uint32_t a;
    asm("{ .reg .u64 t; cvta.to.shared.u64 t, %1; cvt.u32.u64 %0, t; }" : "=r"(a) : "l"(p));
    return a;
}

__device__ __forceinline__ void ldsm_x4(uint32_t r[4], uint32_t addr) {
    asm volatile("ldmatrix.sync.aligned.m8n8.x4.shared.b16 {%0,%1,%2,%3}, [%4];"
                 : "=r"(r[0]), "=r"(r[1]), "=r"(r[2]), "=r"(r[3]) : "r"(addr));
}

__device__ __forceinline__ void mma_bf16(float* c, const uint32_t a[4], const uint32_t* b) {
    asm volatile(
        "mma.sync.aligned.m16n8k16.row.col.f32.bf16.bf16.f32 "
        "{%0,%1,%2,%3}, {%4,%5,%6,%7}, {%8,%9}, {%0,%1,%2,%3};"
        : "+f"(c[0]), "+f"(c[1]), "+f"(c[2]), "+f"(c[3])
        : "r"(a[0]), "r"(a[1]), "r"(a[2]), "r"(a[3]), "r"(b[0]), "r"(b[1]));
}

// ===========================================================================
// bf16 split / transpose-split
// ===========================================================================
__global__ void split_kernel(const float* __restrict__ x,
                             __nv_bfloat16* __restrict__ xh,
                             __nv_bfloat16* __restrict__ xl, int total) {
    int i = blockIdx.x * blockDim.x + threadIdx.x;
    if (i >= total) return;
    float v = x[i];
    __nv_bfloat16 h = __float2bfloat16_rn(v);
    xh[i] = h;
    xl[i] = __float2bfloat16_rn(v - __bfloat162float(h));
}

// W[K,N] row-major -> Th/Tl [N,K] K-major
__global__ __launch_bounds__(1024) void transpose_split_kernel(
    const float* __restrict__ W, __nv_bfloat16* __restrict__ Th,
    __nv_bfloat16* __restrict__ Tl, int K, int N) {
    __shared__ float t[32][33];
    int k = blockIdx.y * 32 + threadIdx.y;
    int n = blockIdx.x * 32 + threadIdx.x;
    t[threadIdx.y][threadIdx.x] = W[(size_t)k * N + n];
    __syncthreads();
    int n2 = blockIdx.x * 32 + threadIdx.y;
    int k2 = blockIdx.y * 32 + threadIdx.x;
    float v = t[threadIdx.x][threadIdx.y];
    __nv_bfloat16 h = __float2bfloat16_rn(v);
    Th[(size_t)n2 * K + k2] = h;
    Tl[(size_t)n2 * K + k2] = __float2bfloat16_rn(v - __bfloat162float(h));
}

// ===========================================================================
// mma.sync GEMM:  C[M,N] = (Ah+Al)[M,K] @ (Bh+Bl)[N,K]^T   (hh + hl + lh)
// CTA 128x128, 8 warps 4(M)x2(N), warp tile 32x64, k-chunk 32 (2 k16 steps).
// SMEM: 4 tiles of [128][40] bf16 (stride 40 -> conflict-free ldmatrix).
// Requires N % 128 == 0, K % 32 == 0.
// ===========================================================================
#define KC 32
#define LDS 40   // bf16 stride (32 + 8 pad)

__global__ __launch_bounds__(256) void gemm_mma_kernel(
    const __nv_bfloat16* __restrict__ Ah, const __nv_bfloat16* __restrict__ Al,
    const __nv_bfloat16* __restrict__ Bh, const __nv_bfloat16* __restrict__ Bl,
    float* __restrict__ C, int M, int N, int K)
{
    __shared__ __nv_bfloat16 sAh[128 * LDS];
    __shared__ __nv_bfloat16 sAl[128 * LDS];
    __shared__ __nv_bfloat16 sBh[128 * LDS];
    __shared__ __nv_bfloat16 sBl[128 * LDS];

    const int tid = threadIdx.x;
    const int warp = tid >> 5;
    const int lane = tid & 31;
    const int wm = warp & 3;          // 0..3 -> 32 rows each
    const int wn = warp >> 2;         // 0..1 -> 64 cols each
    const int m0 = blockIdx.y * 128;
    const int n0 = blockIdx.x * 128;

    // loader mapping: 2 threads per row, 16 cols (2 x uint4) each
    const int lr = tid >> 1;
    const int lh = tid & 1;
    const bool valA = (m0 + lr) < M;
    const uint4 z4 = make_uint4(0, 0, 0, 0);

    // ldmatrix lane mapping
    const int li = lane >> 3;         // matrix index 0..3
    const int lrow = lane & 7;
    // A: matrices (m0,k0),(m8,k0),(m0,k8),(m8,k8)
    const int a_mr = ((li & 1) << 3) + lrow;
    const int a_kc = (li >> 1) << 3;
    // B: matrices (n0,k0),(n0,k8),(n8,k0),(n8,k8)  -> two n8k16 frags
    const int b_nr = ((li >> 1) << 3) + lrow;
    const int b_kc = (li & 1) << 3;

    uint32_t sAh_b = smem_u32(sAh), sAl_b = smem_u32(sAl);
    uint32_t sBh_b = smem_u32(sBh), sBl_b = smem_u32(sBl);

    // per-lane ldmatrix byte offsets (within tile)
    const uint32_t offA = ((wm * 32 + a_mr) * LDS + a_kc) * 2;
    const uint32_t offB = ((wn * 64 + b_nr) * LDS + b_kc) * 2;

    float acc[2][8][4] = {};

    const __nv_bfloat16* gAh = Ah + (size_t)(m0 + lr) * K + lh * 16;
    const __nv_bfloat16* gAl = Al + (size_t)(m0 + lr) * K + lh * 16;
    const __nv_bfloat16* gBh = Bh + (size_t)(n0 + lr) * K + lh * 16;
    const __nv_bfloat16* gBl = Bl + (size_t)(n0 + lr) * K + lh * 16;
    __nv_bfloat16* sa_h = sAh + lr * LDS + lh * 16;
    __nv_bfloat16* sa_l = sAl + lr * LDS + lh * 16;
    __nv_bfloat16* sb_h = sBh + lr * LDS + lh * 16;
    __nv_bfloat16* sb_l = sBl + lr * LDS + lh * 16;

    for (int kc = 0; kc < K; kc += KC) {
        __syncthreads();   // previous iteration's reads done
        {
            const uint4* p;
            p = (const uint4*)(gAh + kc);
            ((uint4*)sa_h)[0] = valA ? p[0] : z4;
            ((uint4*)sa_h)[1] = valA ? p[1] : z4;
            p = (const uint4*)(gAl + kc);
            ((uint4*)sa_l)[0] = valA ? p[0] : z4;
            ((uint4*)sa_l)[1] = valA ? p[1] : z4;
            p = (const uint4*)(gBh + kc);
            ((uint4*)sb_h)[0] = p[0];
            ((uint4*)sb_h)[1] = p[1];
            p = (const uint4*)(gBl + kc);
            ((uint4*)sb_l)[0] = p[0];
            ((uint4*)sb_l)[1] = p[1];
        }
        __syncthreads();

        #pragma unroll
        for (int ks = 0; ks < 2; ks++) {
            const uint32_t kOff = ks * 16 * 2;
            uint32_t ah[2][4], al[2][4];
            #pragma unroll
            for (int mt = 0; mt < 2; mt++) {
                uint32_t o = offA + kOff + mt * (16 * LDS * 2);
                ldsm_x4(ah[mt], sAh_b + o);
                ldsm_x4(al[mt], sAl_b + o);
            }
            uint32_t bh[4][4], bl[4][4];
            #pragma unroll
            for (int p = 0; p < 4; p++) {
                uint32_t o = offB + kOff + p * (16 * LDS * 2);
                ldsm_x4(bh[p], sBh_b + o);
                ldsm_x4(bl[p], sBl_b + o);
            }
            #pragma unroll
            for (int mt = 0; mt < 2; mt++) {
                #pragma unroll
                for (int p = 0; p < 4; p++) {
                    mma_bf16(acc[mt][2 * p],     ah[mt], &bh[p][0]);
                    mma_bf16(acc[mt][2 * p],     ah[mt], &bl[p][0]);
                    mma_bf16(acc[mt][2 * p],     al[mt], &bh[p][0]);
                    mma_bf16(acc[mt][2 * p + 1], ah[mt], &bh[p][2]);
                    mma_bf16(acc[mt][2 * p + 1], ah[mt], &bl[p][2]);
                    mma_bf16(acc[mt][2 * p + 1], al[mt], &bh[p][2]);
                }
            }
        }
    }

    // epilogue
    const int r = lane >> 2;
    const int cq = (lane & 3) * 2;
    #pragma unroll
    for (int mt = 0; mt < 2; mt++) {
        #pragma unroll
        for (int nt = 0; nt < 8; nt++) {
            int grow = m0 + wm * 32 + mt * 16 + r;
            int gcol = n0 + wn * 64 + nt * 8 + cq;
            if (grow < M)
                *(float2*)&C[(size_t)grow * N + gcol] =
                    make_float2(acc[mt][nt][0], acc[mt][nt][1]);
            if (grow + 8 < M)
                *(float2*)&C[(size_t)(grow + 8) * N + gcol] =
                    make_float2(acc[mt][nt][2], acc[mt][nt][3]);
        }
    }
}

// ===========================================================================
// Degree / aggregation / combine (identical to the R1-passing kernel)
// ===========================================================================
__global__ void zero_deg_kernel(float* deg1, float* deg2, int n) {
    int i = blockIdx.x * blockDim.x + threadIdx.x;
    if (i < n) { deg1[i] = 0.f; deg2[i] = 0.f; }
}
__global__ void count_deg_kernel(const int* __restrict__ dst, float* deg, int E) {
    int e = blockIdx.x * blockDim.x + threadIdx.x;
    if (e < E) atomicAdd(&deg[dst[e]], 1.0f);
}
__global__ void dinv_kernel(const float* __restrict__ deg1, const float* __restrict__ deg2,
                            float* dinv1, float* dinv2, int n) {
    int i = blockIdx.x * blockDim.x + threadIdx.x;
    if (i < n) {
        dinv1[i] = rsqrtf(deg1[i] + 1.0f);
        dinv2[i] = rsqrtf(deg2[i] + 1.0f);
    }
}
__global__ void selfloop_kernel(const float* __restrict__ lin, const float* __restrict__ dinv,
                                float* __restrict__ agg, int n, int C) {
    int idx = blockIdx.x * blockDim.x + threadIdx.x;
    int total = n * (C >> 2);
    if (idx >= total) return;
    int row = idx / (C >> 2);
    float w = dinv[row]; w = w * w;
    float4 v = ((const float4*)lin)[idx];
    v.x *= w; v.y *= w; v.z *= w; v.w *= w;
    ((float4*)agg)[idx] = v;
}
__global__ void scatter_kernel(const float* __restrict__ lin, const float* __restrict__ dinv,
                               const int* __restrict__ src, const int* __restrict__ dst,
                               float* __restrict__ agg, int E, int C) {
    int gwarp = (blockIdx.x * blockDim.x + threadIdx.x) >> 5;
    int lane = threadIdx.x & 31;
    if (gwarp >= E) return;
    int s = src[gwarp];
    int d = dst[gwarp];
    float coef = dinv[s] * dinv[d];
    const float4* srow = (const float4*)(lin + (size_t)s * C);
    float* drow = agg + (size_t)d * C;
    int c4n = C >> 2;
    for (int c4 = lane; c4 < c4n; c4 += 32) {
        float4 v = srow[c4];
        atomicAdd(drow + 4 * c4 + 0, v.x * coef);
        atomicAdd(drow + 4 * c4 + 1, v.y * coef);
        atomicAdd(drow + 4 * c4 + 2, v.z * coef);
        atomicAdd(drow + 4 * c4 + 3, v.w * coef);
    }
}
__device__ __forceinline__ float elu1(float x) { return x > 0.f ? x : expm1f(x); }
__global__ void combine_kernel(const float* __restrict__ agg1, const float* __restrict__ b1,
                               const float* __restrict__ agg2, const float* __restrict__ b2,
                               const float* __restrict__ aw,
                               float* __restrict__ out, int n, int C) {
    int idx = blockIdx.x * blockDim.x + threadIdx.x;
    if (idx >= n * C) return;
    int c = idx % C;
    float w0 = 1.0f / (1.0f + expf(aw[2 * c + 1] - aw[2 * c]));
    float v1 = elu1(agg1[idx] + b1[c]);
    float v2 = elu1(agg2[idx] + b2[c]);
    out[idx] = v1 * w0 + v2 * (1.0f - w0);
}

// ===========================================================================
// Host
// ===========================================================================
static void run_layer(const float* x, int n, int Cin, int Cout,
                      const float* Wa, const float* ba,
                      const float* Wb, const float* bb,
                      const float* aw,
                      const int* src1, const int* dst1, int E1,
                      const int* src2, const int* dst2, int E2,
                      float* lin1, float* lin2, float* agg1, float* agg2,
                      float* dinv1, float* dinv2,
                      __nv_bfloat16* xh, __nv_bfloat16* xl,
                      __nv_bfloat16* wth1, __nv_bfloat16* wtl1,
                      __nv_bfloat16* wth2, __nv_bfloat16* wtl2,
                      float* out)
{
    int totin = n * Cin;
    split_kernel<<<(totin + 255) / 256, 256>>>(x, xh, xl, totin);

    dim3 tb(32, 32);
    transpose_split_kernel<<<dim3(Cout / 32, Cin / 32), tb>>>(Wa, wth1, wtl1, Cin, Cout);
    transpose_split_kernel<<<dim3(Cout / 32, Cin / 32), tb>>>(Wb, wth2, wtl2, Cin, Cout);

    dim3 gg(Cout / 128, (n + 127) / 128);
    gemm_mma_kernel<<<gg, 256>>>(xh, xl, wth1, wtl1, lin1, n, Cout, Cin);
    gemm_mma_kernel<<<gg, 256>>>(xh, xl, wth2, wtl2, lin2, n, Cout, Cin);

    int tot4 = n * (Cout >> 2);
    selfloop_kernel<<<(tot4 + 255) / 256, 256>>>(lin1, dinv1, agg1, n, Cout);
    selfloop_kernel<<<(tot4 + 255) / 256, 256>>>(lin2, dinv2, agg2, n, Cout);

    scatter_kernel<<<(E1 + 7) / 8, 256>>>(lin1, dinv1, src1, dst1, agg1, E1, Cout);
    scatter_kernel<<<(E2 + 7) / 8, 256>>>(lin2, dinv2, src2, dst2, agg2, E2, Cout);

    int tot = n * Cout;
    combine_kernel<<<(tot + 255) / 256, 256>>>(agg1, ba, agg2, bb, aw, out, n, Cout);
}

extern "C" void kernel_launch(void* const* d_in, const int* in_sizes, int n_in,
                              void* d_out, int out_size)
{
    const float* x   = (const float*)d_in[0];
    const int*   ei1 = (const int*)d_in[1];
    const int*   ei2 = (const int*)d_in[2];
    const float* W11 = (const float*)d_in[3];  const float* b11 = (const float*)d_in[4];
    const float* W12 = (const float*)d_in[5];  const float* b12 = (const float*)d_in[6];
    const float* W21 = (const float*)d_in[7];  const float* b21 = (const float*)d_in[8];
    const float* W22 = (const float*)d_in[9];  const float* b22 = (const float*)d_in[10];
    const float* W31 = (const float*)d_in[11]; const float* b31 = (const float*)d_in[12];
    const float* W32 = (const float*)d_in[13]; const float* b32 = (const float*)d_in[14];
    const float* aw1 = (const float*)d_in[15];
    const float* aw2 = (const float*)d_in[16];
    const float* aw3 = (const float*)d_in[17];

    int n  = in_sizes[0] / 512;
    int E1 = in_sizes[1] / 2;
    int E2 = in_sizes[2] / 2;

    const int* src1 = ei1;
    const int* dst1 = ei1 + E1;
    const int* src2 = ei2;
    const int* dst2 = ei2 + E2;

    float *lin1, *lin2, *agg1, *agg2, *h, *deg1, *deg2, *dinv1, *dinv2;
    __nv_bfloat16 *xh, *xl, *wth1, *wtl1, *wth2, *wtl2;
    cudaGetSymbolAddress((void**)&lin1,  g_lin1);
    cudaGetSymbolAddress((void**)&lin2,  g_lin2);
    cudaGetSymbolAddress((void**)&agg1,  g_agg1);
    cudaGetSymbolAddress((void**)&agg2,  g_agg2);
    cudaGetSymbolAddress((void**)&h,     g_h);
    cudaGetSymbolAddress((void**)&deg1,  g_deg1);
    cudaGetSymbolAddress((void**)&deg2,  g_deg2);
    cudaGetSymbolAddress((void**)&dinv1, g_dinv1);
    cudaGetSymbolAddress((void**)&dinv2, g_dinv2);
    cudaGetSymbolAddress((void**)&xh,    g_xh);
    cudaGetSymbolAddress((void**)&xl,    g_xl);
    cudaGetSymbolAddress((void**)&wth1,  g_wth1);
    cudaGetSymbolAddress((void**)&wtl1,  g_wtl1);
    cudaGetSymbolAddress((void**)&wth2,  g_wth2);
    cudaGetSymbolAddress((void**)&wtl2,  g_wtl2);

    zero_deg_kernel<<<(n + 255) / 256, 256>>>(deg1, deg2, n);
    count_deg_kernel<<<(E1 + 255) / 256, 256>>>(dst1, deg1, E1);
    count_deg_kernel<<<(E2 + 255) / 256, 256>>>(dst2, deg2, E2);
    dinv_kernel<<<(n + 255) / 256, 256>>>(deg1, deg2, dinv1, dinv2, n);

    run_layer(x, n, 512, 1024, W11, b11, W12, b12, aw1,
              src1, dst1, E1, src2, dst2, E2,
              lin1, lin2, agg1, agg2, dinv1, dinv2,
              xh, xl, wth1, wtl1, wth2, wtl2, h);

    run_layer(h, n, 1024, 512, W21, b21, W22, b22, aw2,
              src1, dst1, E1, src2, dst2, E2,
              lin1, lin2, agg1, agg2, dinv1, dinv2,
              xh, xl, wth1, wtl1, wth2, wtl2, h);

    run_layer(h, n, 512, 128, W31, b31, W32, b32, aw3,
              src1, dst1, E1, src2, dst2, E2,
              lin1, lin2, agg1, agg2, dinv1, dinv2,
              xh, xl, wth1, wtl1, wth2, wtl2, (float*)d_out);
}

// round 4
// speedup vs baseline: 2.5912x; 1.9243x over previous
#include <cuda_runtime.h>
#include <cuda_bf16.h>
#include <cstdint>
#include <math.h>

// ===========================================================================
// GCN2 on GB300: mma.sync bf16 3-term-split GEMMs (fused fp32->bf16 split,
// fused dinv row scaling) + CSR gather aggregation (no atomics on features).
// Layers: 512 -> 1024 -> 512 -> 128, N = 10000 nodes, two edge sets.
// out[d] = dinv[d] * ( sum_{s in N(d)} lin_s[s] + lin_s[d] ),
//   where lin_s = (X@W) * dinv[row]  (computed in the GEMM epilogue).
// ===========================================================================

#define NN 10000
#define CMAX 1024
#define EMAX 200000

__device__ float g_lin1[NN * CMAX];
__device__ float g_lin2[NN * CMAX];
__device__ float g_agg1[NN * CMAX];
__device__ float g_agg2[NN * CMAX];
__device__ float g_h   [NN * CMAX];
__device__ float g_dinv1[NN];
__device__ float g_dinv2[NN];
__device__ int   g_cnt1[NN];
__device__ int   g_cnt2[NN];
__device__ int   g_rp1[NN + 1];
__device__ int   g_rp2[NN + 1];
__device__ int   g_cur1[NN];
__device__ int   g_cur2[NN];
__device__ int   g_col1[EMAX];
__device__ int   g_col2[EMAX];
__device__ __nv_bfloat16 g_wth1[1024 * 1024];
__device__ __nv_bfloat16 g_wtl1[1024 * 1024];
__device__ __nv_bfloat16 g_wth2[1024 * 1024];
__device__ __nv_bfloat16 g_wtl2[1024 * 1024];

// ---------------------------------------------------------------------------
__device__ __forceinline__ uint32_t smem_u32(const void* p) {
    uint32_t a;
    asm("{ .reg .u64 t; cvta.to.shared.u64 t, %1; cvt.u32.u64 %0, t; }" : "=r"(a) : "l"(p));
    return a;
}
__device__ __forceinline__ void ldsm_x4(uint32_t r[4], uint32_t addr) {
    asm volatile("ldmatrix.sync.aligned.m8n8.x4.shared.b16 {%0,%1,%2,%3}, [%4];"
                 : "=r"(r[0]), "=r"(r[1]), "=r"(r[2]), "=r"(r[3]) : "r"(addr));
}
__device__ __forceinline__ void mma_bf16(float* c, const uint32_t a[4], const uint32_t* b) {
    asm volatile(
        "mma.sync.aligned.m16n8k16.row.col.f32.bf16.bf16.f32 "
        "{%0,%1,%2,%3}, {%4,%5,%6,%7}, {%8,%9}, {%0,%1,%2,%3};"
        : "+f"(c[0]), "+f"(c[1]), "+f"(c[2]), "+f"(c[3])
        : "r"(a[0]), "r"(a[1]), "r"(a[2]), "r"(a[3]), "r"(b[0]), "r"(b[1]));
}

// ===========================================================================
// CSR build
// ===========================================================================
__global__ void zero_cnt_kernel(int* c1, int* c2, int n) {
    int i = blockIdx.x * blockDim.x + threadIdx.x;
    if (i < n) { c1[i] = 0; c2[i] = 0; }
}
__global__ void count_kernel(const int* __restrict__ dst1, int E1,
                             const int* __restrict__ dst2, int E2,
                             int* c1, int* c2) {
    int i = blockIdx.x * blockDim.x + threadIdx.x;
    if (i < E1) atomicAdd(&c1[dst1[i]], 1);
    else if (i < E1 + E2) atomicAdd(&c2[dst2[i - E1]], 1);
}

__device__ void scan_one(const int* cnt, int* rp, int* cur, float* dinv, int n,
                         int* buf, int* carry) {
    int tid = threadIdx.x;
    if (tid == 0) *carry = 0;
    __syncthreads();
    for (int base = 0; base < n; base += 1024) {
        int idx = base + tid;
        int x = (idx < n) ? cnt[idx] : 0;
        buf[tid] = x;
        __syncthreads();
        #pragma unroll
        for (int off = 1; off < 1024; off <<= 1) {
            int v = (tid >= off) ? buf[tid - off] : 0;
            __syncthreads();
            buf[tid] += v;
            __syncthreads();
        }
        int excl = buf[tid] - x;
        int c = *carry;
        if (idx < n) {
            rp[idx] = c + excl;
            cur[idx] = c + excl;
            dinv[idx] = rsqrtf((float)x + 1.0f);
        }
        __syncthreads();
        if (tid == 0) *carry = c + buf[1023];
        __syncthreads();
    }
    if (tid == 0) rp[n] = *carry;
    __syncthreads();
}

__global__ __launch_bounds__(1024) void scan_kernel(
    const int* c1, int* rp1, int* cur1, float* dinv1,
    const int* c2, int* rp2, int* cur2, float* dinv2, int n) {
    __shared__ int buf[1024];
    __shared__ int carry;
    scan_one(c1, rp1, cur1, dinv1, n, buf, &carry);
    scan_one(c2, rp2, cur2, dinv2, n, buf, &carry);
}

__global__ void fill_kernel(const int* __restrict__ src1, const int* __restrict__ dst1, int E1,
                            const int* __restrict__ src2, const int* __restrict__ dst2, int E2,
                            int* cur1, int* col1, int* cur2, int* col2) {
    int i = blockIdx.x * blockDim.x + threadIdx.x;
    if (i < E1) {
        int pos = atomicAdd(&cur1[dst1[i]], 1);
        col1[pos] = src1[i];
    } else if (i < E1 + E2) {
        int j = i - E1;
        int pos = atomicAdd(&cur2[dst2[j]], 1);
        col2[pos] = src2[j];
    }
}

// ===========================================================================
// W[K,N] row-major -> Th/Tl [N,K] K-major (bf16 hi/lo)
// ===========================================================================
__global__ __launch_bounds__(1024) void transpose_split_kernel(
    const float* __restrict__ W, __nv_bfloat16* __restrict__ Th,
    __nv_bfloat16* __restrict__ Tl, int K, int N) {
    __shared__ float t[32][33];
    int k = blockIdx.y * 32 + threadIdx.y;
    int n = blockIdx.x * 32 + threadIdx.x;
    t[threadIdx.y][threadIdx.x] = W[(size_t)k * N + n];
    __syncthreads();
    int n2 = blockIdx.x * 32 + threadIdx.y;
    int k2 = blockIdx.y * 32 + threadIdx.x;
    float v = t[threadIdx.x][threadIdx.y];
    __nv_bfloat16 h = __float2bfloat16_rn(v);
    Th[(size_t)n2 * K + k2] = h;
    Tl[(size_t)n2 * K + k2] = __float2bfloat16_rn(v - __bfloat162float(h));
}

// ===========================================================================
// GEMM: C[M,N] = ((A@W) * dinv[row]);  A fp32 [M,K], W split [N,K]^T bf16.
// 3-term split hh+hl+lh. CTA 128x128, 8 warps 4x2, warp tile 32x64, KC=32.
// A is split to hi/lo in the loader (registers). SMEM 40 KB static.
// ===========================================================================
#define KC 32
#define LDS 40

__global__ __launch_bounds__(256) void gemm_mma_kernel(
    const float* __restrict__ A,
    const __nv_bfloat16* __restrict__ Bh, const __nv_bfloat16* __restrict__ Bl,
    const float* __restrict__ dinv,
    float* __restrict__ C, int M, int N, int K)
{
    __shared__ __nv_bfloat16 sAh[128 * LDS];
    __shared__ __nv_bfloat16 sAl[128 * LDS];
    __shared__ __nv_bfloat16 sBh[128 * LDS];
    __shared__ __nv_bfloat16 sBl[128 * LDS];

    const int tid = threadIdx.x;
    const int warp = tid >> 5;
    const int lane = tid & 31;
    const int wm = warp & 3;
    const int wn = warp >> 2;
    const int m0 = blockIdx.y * 128;
    const int n0 = blockIdx.x * 128;

    const int lr = tid >> 1;
    const int lh = tid & 1;
    const bool valA = (m0 + lr) < M;
    const uint4 z4 = make_uint4(0, 0, 0, 0);

    const int li = lane >> 3;
    const int lrow = lane & 7;
    const int a_mr = ((li & 1) << 3) + lrow;
    const int a_kc = (li >> 1) << 3;
    const int b_nr = ((li >> 1) << 3) + lrow;
    const int b_kc = (li & 1) << 3;

    uint32_t sAh_b = smem_u32(sAh), sAl_b = smem_u32(sAl);
    uint32_t sBh_b = smem_u32(sBh), sBl_b = smem_u32(sBl);
    const uint32_t offA = ((wm * 32 + a_mr) * LDS + a_kc) * 2;
    const uint32_t offB = ((wn * 64 + b_nr) * LDS + b_kc) * 2;

    float acc[2][8][4] = {};

    const float* gA = A + (size_t)(m0 + lr) * K + lh * 16;
    const __nv_bfloat16* gBh = Bh + (size_t)(n0 + lr) * K + lh * 16;
    const __nv_bfloat16* gBl = Bl + (size_t)(n0 + lr) * K + lh * 16;
    __nv_bfloat16* sa_h = sAh + lr * LDS + lh * 16;
    __nv_bfloat16* sa_l = sAl + lr * LDS + lh * 16;
    __nv_bfloat16* sb_h = sBh + lr * LDS + lh * 16;
    __nv_bfloat16* sb_l = sBl + lr * LDS + lh * 16;

    for (int kc = 0; kc < K; kc += KC) {
        __syncthreads();
        {
            // A: read 16 fp32, split to bf16 hi/lo in registers
            float f[16];
            if (valA) {
                const float4* p = (const float4*)(gA + kc);
                #pragma unroll
                for (int j = 0; j < 4; j++) {
                    float4 v = p[j];
                    f[4 * j + 0] = v.x; f[4 * j + 1] = v.y;
                    f[4 * j + 2] = v.z; f[4 * j + 3] = v.w;
                }
            } else {
                #pragma unroll
                for (int j = 0; j < 16; j++) f[j] = 0.f;
            }
            __nv_bfloat16 hv[16], lv[16];
            #pragma unroll
            for (int j = 0; j < 16; j++) {
                __nv_bfloat16 h = __float2bfloat16_rn(f[j]);
                hv[j] = h;
                lv[j] = __float2bfloat16_rn(f[j] - __bfloat162float(h));
            }
            ((uint4*)sa_h)[0] = ((uint4*)hv)[0];
            ((uint4*)sa_h)[1] = ((uint4*)hv)[1];
            ((uint4*)sa_l)[0] = ((uint4*)lv)[0];
            ((uint4*)sa_l)[1] = ((uint4*)lv)[1];

            const uint4* pb;
            pb = (const uint4*)(gBh + kc);
            ((uint4*)sb_h)[0] = pb[0];
            ((uint4*)sb_h)[1] = pb[1];
            pb = (const uint4*)(gBl + kc);
            ((uint4*)sb_l)[0] = pb[0];
            ((uint4*)sb_l)[1] = pb[1];
        }
        __syncthreads();

        #pragma unroll
        for (int ks = 0; ks < 2; ks++) {
            const uint32_t kOff = ks * 16 * 2;
            uint32_t ah[2][4], al[2][4];
            #pragma unroll
            for (int mt = 0; mt < 2; mt++) {
                uint32_t o = offA + kOff + mt * (16 * LDS * 2);
                ldsm_x4(ah[mt], sAh_b + o);
                ldsm_x4(al[mt], sAl_b + o);
            }
            uint32_t bh[4][4], bl[4][4];
            #pragma unroll
            for (int p = 0; p < 4; p++) {
                uint32_t o = offB + kOff + p * (16 * LDS * 2);
                ldsm_x4(bh[p], sBh_b + o);
                ldsm_x4(bl[p], sBl_b + o);
            }
            #pragma unroll
            for (int mt = 0; mt < 2; mt++) {
                #pragma unroll
                for (int p = 0; p < 4; p++) {
                    mma_bf16(acc[mt][2 * p],     ah[mt], &bh[p][0]);
                    mma_bf16(acc[mt][2 * p],     ah[mt], &bl[p][0]);
                    mma_bf16(acc[mt][2 * p],     al[mt], &bh[p][0]);
                    mma_bf16(acc[mt][2 * p + 1], ah[mt], &bh[p][2]);
                    mma_bf16(acc[mt][2 * p + 1], ah[mt], &bl[p][2]);
                    mma_bf16(acc[mt][2 * p + 1], al[mt], &bh[p][2]);
                }
            }
        }
    }

    // epilogue: scale row by dinv[row], store
    const int r = lane >> 2;
    const int cq = (lane & 3) * 2;
    #pragma unroll
    for (int mt = 0; mt < 2; mt++) {
        int grow = m0 + wm * 32 + mt * 16 + r;
        float dv0 = (grow < M)     ? dinv[grow]     : 0.f;
        float dv1 = (grow + 8 < M) ? dinv[grow + 8] : 0.f;
        #pragma unroll
        for (int nt = 0; nt < 8; nt++) {
            int gcol = n0 + wn * 64 + nt * 8 + cq;
            if (grow < M)
                *(float2*)&C[(size_t)grow * N + gcol] =
                    make_float2(acc[mt][nt][0] * dv0, acc[mt][nt][1] * dv0);
            if (grow + 8 < M)
                *(float2*)&C[(size_t)(grow + 8) * N + gcol] =
                    make_float2(acc[mt][nt][2] * dv1, acc[mt][nt][3] * dv1);
        }
    }
}

// ===========================================================================
// CSR gather: agg[d,:] = dinv[d] * ( sum_{s in N(d)} lin[s,:] + lin[d,:] )
// One warp per node; CPL = C/128 float4 per lane.
// ===========================================================================
template <int CPL>
__global__ __launch_bounds__(256) void gather_kernel(
    const float* __restrict__ lin, const float* __restrict__ dinv,
    const int* __restrict__ rowptr, const int* __restrict__ col,
    float* __restrict__ agg, int n, int C)
{
    int gwarp = (blockIdx.x * blockDim.x + threadIdx.x) >> 5;
    int lane = threadIdx.x & 31;
    if (gwarp >= n) return;
    int d = gwarp;

    float4 acc[CPL];
    const float4* selfrow = (const float4*)(lin + (size_t)d * C);
    #pragma unroll
    for (int j = 0; j < CPL; j++) acc[j] = selfrow[lane + j * 32];

    int e = rowptr[d];
    int end = rowptr[d + 1];

    if (CPL <= 2) {
        // unroll 4 edges for MLP
        for (; e + 3 < end; e += 4) {
            const float4* r0 = (const float4*)(lin + (size_t)col[e]     * C);
            const float4* r1 = (const float4*)(lin + (size_t)col[e + 1] * C);
            const float4* r2 = (const float4*)(lin + (size_t)col[e + 2] * C);
            const float4* r3 = (const float4*)(lin + (size_t)col[e + 3] * C);
            #pragma unroll
            for (int j = 0; j < CPL; j++) {
                float4 v0 = r0[lane + j * 32];
                float4 v1 = r1[lane + j * 32];
                float4 v2 = r2[lane + j * 32];
                float4 v3 = r3[lane + j * 32];
                acc[j].x += (v0.x + v1.x) + (v2.x + v3.x);
                acc[j].y += (v0.y + v1.y) + (v2.y + v3.y);
                acc[j].z += (v0.z + v1.z) + (v2.z + v3.z);
                acc[j].w += (v0.w + v1.w) + (v2.w + v3.w);
            }
        }
    } else {
        for (; e + 1 < end; e += 2) {
            const float4* r0 = (const float4*)(lin + (size_t)col[e]     * C);
            const float4* r1 = (const float4*)(lin + (size_t)col[e + 1] * C);
            #pragma unroll
            for (int j = 0; j < CPL; j++) {
                float4 v0 = r0[lane + j * 32];
                float4 v1 = r1[lane + j * 32];
                acc[j].x += v0.x + v1.x;
                acc[j].y += v0.y + v1.y;
                acc[j].z += v0.z + v1.z;
                acc[j].w += v0.w + v1.w;
            }
        }
    }
    for (; e < end; e++) {
        const float4* r0 = (const float4*)(lin + (size_t)col[e] * C);
        #pragma unroll
        for (int j = 0; j < CPL; j++) {
            float4 v = r0[lane + j * 32];
            acc[j].x += v.x; acc[j].y += v.y; acc[j].z += v.z; acc[j].w += v.w;
        }
    }

    float dv = dinv[d];
    float4* out = (float4*)(agg + (size_t)d * C);
    #pragma unroll
    for (int j = 0; j < CPL; j++) {
        acc[j].x *= dv; acc[j].y *= dv; acc[j].z *= dv; acc[j].w *= dv;
        out[lane + j * 32] = acc[j];
    }
}

// ===========================================================================
// Combine: out = elu(agg1+b1)*w0 + elu(agg2+b2)*(1-w0)
// ===========================================================================
__device__ __forceinline__ float elu1(float x) { return x > 0.f ? x : expm1f(x); }

__global__ void combine_kernel(const float* __restrict__ agg1, const float* __restrict__ b1,
                               const float* __restrict__ agg2, const float* __restrict__ b2,
                               const float* __restrict__ aw,
                               float* __restrict__ out, int n, int C) {
    int idx = blockIdx.x * blockDim.x + threadIdx.x;
    if (idx >= n * C) return;
    int c = idx % C;
    float w0 = 1.0f / (1.0f + expf(aw[2 * c + 1] - aw[2 * c]));
    float v1 = elu1(agg1[idx] + b1[c]);
    float v2 = elu1(agg2[idx] + b2[c]);
    out[idx] = v1 * w0 + v2 * (1.0f - w0);
}

// ===========================================================================
// Host
// ===========================================================================
static void run_layer(const float* x, int n, int Cin, int Cout,
                      const float* Wa, const float* ba,
                      const float* Wb, const float* bb,
                      const float* aw,
                      float* lin1, float* lin2, float* agg1, float* agg2,
                      float* dinv1, float* dinv2,
                      const int* rp1, const int* col1,
                      const int* rp2, const int* col2,
                      __nv_bfloat16* wth1, __nv_bfloat16* wtl1,
                      __nv_bfloat16* wth2, __nv_bfloat16* wtl2,
                      float* out)
{
    dim3 tb(32, 32);
    transpose_split_kernel<<<dim3(Cout / 32, Cin / 32), tb>>>(Wa, wth1, wtl1, Cin, Cout);
    transpose_split_kernel<<<dim3(Cout / 32, Cin / 32), tb>>>(Wb, wth2, wtl2, Cin, Cout);

    dim3 gg(Cout / 128, (n + 127) / 128);
    gemm_mma_kernel<<<gg, 256>>>(x, wth1, wtl1, dinv1, lin1, n, Cout, Cin);
    gemm_mma_kernel<<<gg, 256>>>(x, wth2, wtl2, dinv2, lin2, n, Cout, Cin);

    int gblocks = (n * 32 + 255) / 256;
    if (Cout == 1024) {
        gather_kernel<8><<<gblocks, 256>>>(lin1, dinv1, rp1, col1, agg1, n, Cout);
        gather_kernel<8><<<gblocks, 256>>>(lin2, dinv2, rp2, col2, agg2, n, Cout);
    } else if (Cout == 512) {
        gather_kernel<4><<<gblocks, 256>>>(lin1, dinv1, rp1, col1, agg1, n, Cout);
        gather_kernel<4><<<gblocks, 256>>>(lin2, dinv2, rp2, col2, agg2, n, Cout);
    } else {
        gather_kernel<1><<<gblocks, 256>>>(lin1, dinv1, rp1, col1, agg1, n, Cout);
        gather_kernel<1><<<gblocks, 256>>>(lin2, dinv2, rp2, col2, agg2, n, Cout);
    }

    int tot = n * Cout;
    combine_kernel<<<(tot + 255) / 256, 256>>>(agg1, ba, agg2, bb, aw, out, n, Cout);
}

extern "C" void kernel_launch(void* const* d_in, const int* in_sizes, int n_in,
                              void* d_out, int out_size)
{
    const float* x   = (const float*)d_in[0];
    const int*   ei1 = (const int*)d_in[1];
    const int*   ei2 = (const int*)d_in[2];
    const float* W11 = (const float*)d_in[3];  const float* b11 = (const float*)d_in[4];
    const float* W12 = (const float*)d_in[5];  const float* b12 = (const float*)d_in[6];
    const float* W21 = (const float*)d_in[7];  const float* b21 = (const float*)d_in[8];
    const float* W22 = (const float*)d_in[9];  const float* b22 = (const float*)d_in[10];
    const float* W31 = (const float*)d_in[11]; const float* b31 = (const float*)d_in[12];
    const float* W32 = (const float*)d_in[13]; const float* b32 = (const float*)d_in[14];
    const float* aw1 = (const float*)d_in[15];
    const float* aw2 = (const float*)d_in[16];
    const float* aw3 = (const float*)d_in[17];

    int n  = in_sizes[0] / 512;
    int E1 = in_sizes[1] / 2;
    int E2 = in_sizes[2] / 2;

    const int* src1 = ei1;
    const int* dst1 = ei1 + E1;
    const int* src2 = ei2;
    const int* dst2 = ei2 + E2;

    float *lin1, *lin2, *agg1, *agg2, *h, *dinv1, *dinv2;
    int *cnt1, *cnt2, *rp1, *rp2, *cur1, *cur2, *col1, *col2;
    __nv_bfloat16 *wth1, *wtl1, *wth2, *wtl2;
    cudaGetSymbolAddress((void**)&lin1,  g_lin1);
    cudaGetSymbolAddress((void**)&lin2,  g_lin2);
    cudaGetSymbolAddress((void**)&agg1,  g_agg1);
    cudaGetSymbolAddress((void**)&agg2,  g_agg2);
    cudaGetSymbolAddress((void**)&h,     g_h);
    cudaGetSymbolAddress((void**)&dinv1, g_dinv1);
    cudaGetSymbolAddress((void**)&dinv2, g_dinv2);
    cudaGetSymbolAddress((void**)&cnt1,  g_cnt1);
    cudaGetSymbolAddress((void**)&cnt2,  g_cnt2);
    cudaGetSymbolAddress((void**)&rp1,   g_rp1);
    cudaGetSymbolAddress((void**)&rp2,   g_rp2);
    cudaGetSymbolAddress((void**)&cur1,  g_cur1);
    cudaGetSymbolAddress((void**)&cur2,  g_cur2);
    cudaGetSymbolAddress((void**)&col1,  g_col1);
    cudaGetSymbolAddress((void**)&col2,  g_col2);
    cudaGetSymbolAddress((void**)&wth1,  g_wth1);
    cudaGetSymbolAddress((void**)&wtl1,  g_wtl1);
    cudaGetSymbolAddress((void**)&wth2,  g_wth2);
    cudaGetSymbolAddress((void**)&wtl2,  g_wtl2);

    // CSR build
    zero_cnt_kernel<<<(n + 255) / 256, 256>>>(cnt1, cnt2, n);
    count_kernel<<<(E1 + E2 + 255) / 256, 256>>>(dst1, E1, dst2, E2, cnt1, cnt2);
    scan_kernel<<<1, 1024>>>(cnt1, rp1, cur1, dinv1, cnt2, rp2, cur2, dinv2, n);
    fill_kernel<<<(E1 + E2 + 255) / 256, 256>>>(src1, dst1, E1, src2, dst2, E2,
                                                cur1, col1, cur2, col2);

    run_layer(x, n, 512, 1024, W11, b11, W12, b12, aw1,
              lin1, lin2, agg1, agg2, dinv1, dinv2,
              rp1, col1, rp2, col2, wth1, wtl1, wth2, wtl2, h);

    run_layer(h, n, 1024, 512, W21, b21, W22, b22, aw2,
              lin1, lin2, agg1, agg2, dinv1, dinv2,
              rp1, col1, rp2, col2, wth1, wtl1, wth2, wtl2, h);

    run_layer(h, n, 512, 128, W31, b31, W32, b32, aw3,
              lin1, lin2, agg1, agg2, dinv1, dinv2,
              rp1, col1, rp2, col2, wth1, wtl1, wth2, wtl2, (float*)d_out);
}

// round 5
// speedup vs baseline: 2.8421x; 1.0968x over previous
#include <cuda_runtime.h>
#include <cuda_bf16.h>
#include <cstdint>
#include <math.h>

// ===========================================================================
// GCN2 on GB300: software-pipelined mma.sync bf16 3-term-split GEMMs
// (fused fp32->bf16 split + dinv row scale, both branches in one launch)
// + fused dual-CSR gather / bias / ELU / softmax-combine.
// Layers: 512 -> 1024 -> 512 -> 128, N = 10000 nodes, two edge sets.
// ===========================================================================

#define NN 10000
#define CMAX 1024
#define EMAX 200000

__device__ float g_lin1[NN * CMAX];
__device__ float g_lin2[NN * CMAX];
__device__ float g_h   [NN * CMAX];
__device__ float g_dinv1[NN];
__device__ float g_dinv2[NN];
__device__ int   g_cnt1[NN];
__device__ int   g_cnt2[NN];
__device__ int   g_rp1[NN + 1];
__device__ int   g_rp2[NN + 1];
__device__ int   g_cur1[NN];
__device__ int   g_cur2[NN];
__device__ int   g_col1[EMAX];
__device__ int   g_col2[EMAX];
__device__ __nv_bfloat16 g_wth1[1024 * 1024];
__device__ __nv_bfloat16 g_wtl1[1024 * 1024];
__device__ __nv_bfloat16 g_wth2[1024 * 1024];
__device__ __nv_bfloat16 g_wtl2[1024 * 1024];

// ---------------------------------------------------------------------------
__device__ __forceinline__ uint32_t smem_u32(const void* p) {
    uint32_t a;
    asm("{ .reg .u64 t; cvta.to.shared.u64 t, %1; cvt.u32.u64 %0, t; }" : "=r"(a) : "l"(p));
    return a;
}
__device__ __forceinline__ void ldsm_x4(uint32_t r[4], uint32_t addr) {
    asm volatile("ldmatrix.sync.aligned.m8n8.x4.shared.b16 {%0,%1,%2,%3}, [%4];"
                 : "=r"(r[0]), "=r"(r[1]), "=r"(r[2]), "=r"(r[3]) : "r"(addr));
}
__device__ __forceinline__ void mma_bf16(float* c, const uint32_t a[4], const uint32_t* b) {
    asm volatile(
        "mma.sync.aligned.m16n8k16.row.col.f32.bf16.bf16.f32 "
        "{%0,%1,%2,%3}, {%4,%5,%6,%7}, {%8,%9}, {%0,%1,%2,%3};"
        : "+f"(c[0]), "+f"(c[1]), "+f"(c[2]), "+f"(c[3])
        : "r"(a[0]), "r"(a[1]), "r"(a[2]), "r"(a[3]), "r"(b[0]), "r"(b[1]));
}

// ===========================================================================
// CSR build
// ===========================================================================
__global__ void zero_cnt_kernel(int* c1, int* c2, int n) {
    int i = blockIdx.x * blockDim.x + threadIdx.x;
    if (i < n) { c1[i] = 0; c2[i] = 0; }
}
__global__ void count_kernel(const int* __restrict__ dst1, int E1,
                             const int* __restrict__ dst2, int E2,
                             int* c1, int* c2) {
    int i = blockIdx.x * blockDim.x + threadIdx.x;
    if (i < E1) atomicAdd(&c1[dst1[i]], 1);
    else if (i < E1 + E2) atomicAdd(&c2[dst2[i - E1]], 1);
}

// grid = 2 blocks, one per edge set
__global__ __launch_bounds__(1024) void scan_kernel(
    const int* c1, int* rp1, int* cur1, float* dinv1,
    const int* c2, int* rp2, int* cur2, float* dinv2, int n) {
    __shared__ int buf[1024];
    __shared__ int carry;
    const int* cnt = blockIdx.x ? c2 : c1;
    int* rp   = blockIdx.x ? rp2   : rp1;
    int* cur  = blockIdx.x ? cur2  : cur1;
    float* dv = blockIdx.x ? dinv2 : dinv1;

    int tid = threadIdx.x;
    if (tid == 0) carry = 0;
    __syncthreads();
    for (int base = 0; base < n; base += 1024) {
        int idx = base + tid;
        int x = (idx < n) ? cnt[idx] : 0;
        buf[tid] = x;
        __syncthreads();
        #pragma unroll
        for (int off = 1; off < 1024; off <<= 1) {
            int v = (tid >= off) ? buf[tid - off] : 0;
            __syncthreads();
            buf[tid] += v;
            __syncthreads();
        }
        int excl = buf[tid] - x;
        int c = carry;
        if (idx < n) {
            rp[idx] = c + excl;
            cur[idx] = c + excl;
            dv[idx] = rsqrtf((float)x + 1.0f);
        }
        __syncthreads();
        if (tid == 0) carry = c + buf[1023];
        __syncthreads();
    }
    if (tid == 0) rp[n] = carry;
}

__global__ void fill_kernel(const int* __restrict__ src1, const int* __restrict__ dst1, int E1,
                            const int* __restrict__ src2, const int* __restrict__ dst2, int E2,
                            int* cur1, int* col1, int* cur2, int* col2) {
    int i = blockIdx.x * blockDim.x + threadIdx.x;
    if (i < E1) {
        int pos = atomicAdd(&cur1[dst1[i]], 1);
        col1[pos] = src1[i];
    } else if (i < E1 + E2) {
        int j = i - E1;
        int pos = atomicAdd(&cur2[dst2[j]], 1);
        col2[pos] = src2[j];
    }
}

// ===========================================================================
// W[K,N] row-major -> Th/Tl [N,K] K-major (bf16 hi/lo)
// ===========================================================================
__global__ __launch_bounds__(1024) void transpose_split_kernel(
    const float* __restrict__ W, __nv_bfloat16* __restrict__ Th,
    __nv_bfloat16* __restrict__ Tl, int K, int N) {
    __shared__ float t[32][33];
    int k = blockIdx.y * 32 + threadIdx.y;
    int n = blockIdx.x * 32 + threadIdx.x;
    t[threadIdx.y][threadIdx.x] = W[(size_t)k * N + n];
    __syncthreads();
    int n2 = blockIdx.x * 32 + threadIdx.y;
    int k2 = blockIdx.y * 32 + threadIdx.x;
    float v = t[threadIdx.x][threadIdx.y];
    __nv_bfloat16 h = __float2bfloat16_rn(v);
    Th[(size_t)n2 * K + k2] = h;
    Tl[(size_t)n2 * K + k2] = __float2bfloat16_rn(v - __bfloat162float(h));
}

// ===========================================================================
// GEMM (both branches via blockIdx.z):
// C[M,N] = ((A@W) * dinv[row]); A fp32 [M,K]; W split [N,K]^T bf16.
// 3-term split hh+hl+lh. CTA 128x128, 8 warps 4x2, KC=32, register-prefetch
// software pipeline (LDGs for chunk i+1 issued before chunk i's MMAs).
// ===========================================================================
#define KC 32
#define LDS 40

__global__ __launch_bounds__(256) void gemm_mma_kernel(
    const float* __restrict__ A,
    const __nv_bfloat16* __restrict__ Bh0, const __nv_bfloat16* __restrict__ Bl0,
    const __nv_bfloat16* __restrict__ Bh1, const __nv_bfloat16* __restrict__ Bl1,
    const float* __restrict__ dinv0, const float* __restrict__ dinv1v,
    float* __restrict__ C0, float* __restrict__ C1,
    int M, int N, int K)
{
    const int br = blockIdx.z;
    const __nv_bfloat16* Bh = br ? Bh1 : Bh0;
    const __nv_bfloat16* Bl = br ? Bl1 : Bl0;
    const float* dinv = br ? dinv1v : dinv0;
    float* C = br ? C1 : C0;

    __shared__ __nv_bfloat16 sAh[128 * LDS];
    __shared__ __nv_bfloat16 sAl[128 * LDS];
    __shared__ __nv_bfloat16 sBh[128 * LDS];
    __shared__ __nv_bfloat16 sBl[128 * LDS];

    const int tid = threadIdx.x;
    const int warp = tid >> 5;
    const int lane = tid & 31;
    const int wm = warp & 3;
    const int wn = warp >> 2;
    const int m0 = blockIdx.y * 128;
    const int n0 = blockIdx.x * 128;

    const int lr = tid >> 1;
    const int lh = tid & 1;
    const bool valA = (m0 + lr) < M;

    const int li = lane >> 3;
    const int lrow = lane & 7;
    const int a_mr = ((li & 1) << 3) + lrow;
    const int a_kc = (li >> 1) << 3;
    const int b_nr = ((li >> 1) << 3) + lrow;
    const int b_kc = (li & 1) << 3;

    uint32_t sAh_b = smem_u32(sAh), sAl_b = smem_u32(sAl);
    uint32_t sBh_b = smem_u32(sBh), sBl_b = smem_u32(sBl);
    const uint32_t offA = ((wm * 32 + a_mr) * LDS + a_kc) * 2;
    const uint32_t offB = ((wn * 64 + b_nr) * LDS + b_kc) * 2;

    float acc[2][8][4] = {};

    const float* gA = A + (size_t)(m0 + lr) * K + lh * 16;
    const __nv_bfloat16* gBh = Bh + (size_t)(n0 + lr) * K + lh * 16;
    const __nv_bfloat16* gBl = Bl + (size_t)(n0 + lr) * K + lh * 16;
    __nv_bfloat16* sa_h = sAh + lr * LDS + lh * 16;
    __nv_bfloat16* sa_l = sAl + lr * LDS + lh * 16;
    __nv_bfloat16* sb_h = sBh + lr * LDS + lh * 16;
    __nv_bfloat16* sb_l = sBl + lr * LDS + lh * 16;

    float fA[16];
    uint4 rbh[2], rbl[2];

    auto load_g = [&](int kc) {
        if (valA) {
            const float4* p = (const float4*)(gA + kc);
            #pragma unroll
            for (int j = 0; j < 4; j++) {
                float4 v = p[j];
                fA[4 * j + 0] = v.x; fA[4 * j + 1] = v.y;
                fA[4 * j + 2] = v.z; fA[4 * j + 3] = v.w;
            }
        } else {
            #pragma unroll
            for (int j = 0; j < 16; j++) fA[j] = 0.f;
        }
        const uint4* pb = (const uint4*)(gBh + kc);
        rbh[0] = pb[0]; rbh[1] = pb[1];
        pb = (const uint4*)(gBl + kc);
        rbl[0] = pb[0]; rbl[1] = pb[1];
    };

    load_g(0);

    for (int kc = 0; kc < K; kc += KC) {
        // store prefetched chunk (convert A in regs)
        {
            __nv_bfloat16 hv[16], lv[16];
            #pragma unroll
            for (int j = 0; j < 16; j++) {
                __nv_bfloat16 h = __float2bfloat16_rn(fA[j]);
                hv[j] = h;
                lv[j] = __float2bfloat16_rn(fA[j] - __bfloat162float(h));
            }
            ((uint4*)sa_h)[0] = ((uint4*)hv)[0];
            ((uint4*)sa_h)[1] = ((uint4*)hv)[1];
            ((uint4*)sa_l)[0] = ((uint4*)lv)[0];
            ((uint4*)sa_l)[1] = ((uint4*)lv)[1];
            ((uint4*)sb_h)[0] = rbh[0];
            ((uint4*)sb_h)[1] = rbh[1];
            ((uint4*)sb_l)[0] = rbl[0];
            ((uint4*)sb_l)[1] = rbl[1];
        }
        __syncthreads();

        // issue next chunk's LDGs before the MMA block (latency hidden by MMAs)
        if (kc + KC < K) load_g(kc + KC);

        #pragma unroll
        for (int ks = 0; ks < 2; ks++) {
            const uint32_t kOff = ks * 16 * 2;
            uint32_t ah[2][4], al[2][4];
            #pragma unroll
            for (int mt = 0; mt < 2; mt++) {
                uint32_t o = offA + kOff + mt * (16 * LDS * 2);
                ldsm_x4(ah[mt], sAh_b + o);
                ldsm_x4(al[mt], sAl_b + o);
            }
            uint32_t bh[4][4], bl[4][4];
            #pragma unroll
            for (int p = 0; p < 4; p++) {
                uint32_t o = offB + kOff + p * (16 * LDS * 2);
                ldsm_x4(bh[p], sBh_b + o);
                ldsm_x4(bl[p], sBl_b + o);
            }
            #pragma unroll
            for (int mt = 0; mt < 2; mt++) {
                #pragma unroll
                for (int p = 0; p < 4; p++) {
                    mma_bf16(acc[mt][2 * p],     ah[mt], &bh[p][0]);
                    mma_bf16(acc[mt][2 * p],     ah[mt], &bl[p][0]);
                    mma_bf16(acc[mt][2 * p],     al[mt], &bh[p][0]);
                    mma_bf16(acc[mt][2 * p + 1], ah[mt], &bh[p][2]);
                    mma_bf16(acc[mt][2 * p + 1], ah[mt], &bl[p][2]);
                    mma_bf16(acc[mt][2 * p + 1], al[mt], &bh[p][2]);
                }
            }
        }
        __syncthreads();
    }

    // epilogue: scale row by dinv[row], store
    const int r = lane >> 2;
    const int cq = (lane & 3) * 2;
    #pragma unroll
    for (int mt = 0; mt < 2; mt++) {
        int grow = m0 + wm * 32 + mt * 16 + r;
        float dv0 = (grow < M)     ? dinv[grow]     : 0.f;
        float dv1 = (grow + 8 < M) ? dinv[grow + 8] : 0.f;
        #pragma unroll
        for (int nt = 0; nt < 8; nt++) {
            int gcol = n0 + wn * 64 + nt * 8 + cq;
            if (grow < M)
                *(float2*)&C[(size_t)grow * N + gcol] =
                    make_float2(acc[mt][nt][0] * dv0, acc[mt][nt][1] * dv0);
            if (grow + 8 < M)
                *(float2*)&C[(size_t)(grow + 8) * N + gcol] =
                    make_float2(acc[mt][nt][2] * dv1, acc[mt][nt][3] * dv1);
        }
    }
}

// ===========================================================================
// Fused dual gather + bias + ELU + softmax combine. One warp per node.
// out[d,c] = elu(dinv1[d]*S1 + b1[c])*w0(c) + elu(dinv2[d]*S2 + b2[c])*(1-w0)
//   Sk = lin_k[d,c] + sum_{s in CSRk(d)} lin_k[s,c]   (lin already * dinv[row])
// ===========================================================================
__device__ __forceinline__ float elu1(float x) { return x > 0.f ? x : expm1f(x); }

template <int CPL>
__global__ __launch_bounds__(256) void gather_combine_kernel(
    const float* __restrict__ lin1, const float* __restrict__ lin2,
    const float* __restrict__ dinv1, const float* __restrict__ dinv2,
    const int* __restrict__ rp1, const int* __restrict__ col1,
    const int* __restrict__ rp2, const int* __restrict__ col2,
    const float* __restrict__ b1, const float* __restrict__ b2,
    const float* __restrict__ aw,
    float* __restrict__ out, int n, int C)
{
    int gwarp = (blockIdx.x * blockDim.x + threadIdx.x) >> 5;
    int lane = threadIdx.x & 31;
    if (gwarp >= n) return;
    int d = gwarp;

    float4 acc1[CPL], acc2[CPL];
    {
        const float4* s1 = (const float4*)(lin1 + (size_t)d * C);
        const float4* s2 = (const float4*)(lin2 + (size_t)d * C);
        #pragma unroll
        for (int j = 0; j < CPL; j++) { acc1[j] = s1[lane + j * 32]; acc2[j] = s2[lane + j * 32]; }
    }

    // CSR 1
    {
        int e = rp1[d], end = rp1[d + 1];
        for (; e + 1 < end; e += 2) {
            const float4* r0 = (const float4*)(lin1 + (size_t)col1[e]     * C);
            const float4* r1 = (const float4*)(lin1 + (size_t)col1[e + 1] * C);
            #pragma unroll
            for (int j = 0; j < CPL; j++) {
                float4 v0 = r0[lane + j * 32];
                float4 v1 = r1[lane + j * 32];
                acc1[j].x += v0.x + v1.x; acc1[j].y += v0.y + v1.y;
                acc1[j].z += v0.z + v1.z; acc1[j].w += v0.w + v1.w;
            }
        }
        if (e < end) {
            const float4* r0 = (const float4*)(lin1 + (size_t)col1[e] * C);
            #pragma unroll
            for (int j = 0; j < CPL; j++) {
                float4 v = r0[lane + j * 32];
                acc1[j].x += v.x; acc1[j].y += v.y; acc1[j].z += v.z; acc1[j].w += v.w;
            }
        }
    }
    // CSR 2
    {
        int e = rp2[d], end = rp2[d + 1];
        for (; e + 1 < end; e += 2) {
            const float4* r0 = (const float4*)(lin2 + (size_t)col2[e]     * C);
            const float4* r1 = (const float4*)(lin2 + (size_t)col2[e + 1] * C);
            #pragma unroll
            for (int j = 0; j < CPL; j++) {
                float4 v0 = r0[lane + j * 32];
                float4 v1 = r1[lane + j * 32];
                acc2[j].x += v0.x + v1.x; acc2[j].y += v0.y + v1.y;
                acc2[j].z += v0.z + v1.z; acc2[j].w += v0.w + v1.w;
            }
        }
        if (e < end) {
            const float4* r0 = (const float4*)(lin2 + (size_t)col2[e] * C);
            #pragma unroll
            for (int j = 0; j < CPL; j++) {
                float4 v = r0[lane + j * 32];
                acc2[j].x += v.x; acc2[j].y += v.y; acc2[j].z += v.z; acc2[j].w += v.w;
            }
        }
    }

    float dv1 = dinv1[d];
    float dv2 = dinv2[d];
    float4* o = (float4*)(out + (size_t)d * C);
    #pragma unroll
    for (int j = 0; j < CPL; j++) {
        int ci = lane + j * 32;            // float4 index -> channels 4ci..4ci+3
        float4 bb1 = ((const float4*)b1)[ci];
        float4 bb2 = ((const float4*)b2)[ci];
        float4 aw0 = ((const float4*)aw)[2 * ci];       // aw[4ci..4ci+1][0..1]
        float4 aw1 = ((const float4*)aw)[2 * ci + 1];   // aw[4ci+2..4ci+3][0..1]
        float w0x = 1.0f / (1.0f + expf(aw0.y - aw0.x));
        float w0y = 1.0f / (1.0f + expf(aw0.w - aw0.z));
        float w0z = 1.0f / (1.0f + expf(aw1.y - aw1.x));
        float w0w = 1.0f / (1.0f + expf(aw1.w - aw1.z));
        float4 r;
        r.x = elu1(acc1[j].x * dv1 + bb1.x) * w0x + elu1(acc2[j].x * dv2 + bb2.x) * (1.f - w0x);
        r.y = elu1(acc1[j].y * dv1 + bb1.y) * w0y + elu1(acc2[j].y * dv2 + bb2.y) * (1.f - w0y);
        r.z = elu1(acc1[j].z * dv1 + bb1.z) * w0z + elu1(acc2[j].z * dv2 + bb2.z) * (1.f - w0z);
        r.w = elu1(acc1[j].w * dv1 + bb1.w) * w0w + elu1(acc2[j].w * dv2 + bb2.w) * (1.f - w0w);
        o[ci] = r;
    }
}

// ===========================================================================
// Host
// ===========================================================================
static void run_layer(const float* x, int n, int Cin, int Cout,
                      const float* Wa, const float* ba,
                      const float* Wb, const float* bb,
                      const float* aw,
                      float* lin1, float* lin2,
                      float* dinv1, float* dinv2,
                      const int* rp1, const int* col1,
                      const int* rp2, const int* col2,
                      __nv_bfloat16* wth1, __nv_bfloat16* wtl1,
                      __nv_bfloat16* wth2, __nv_bfloat16* wtl2,
                      float* out)
{
    dim3 tb(32, 32);
    transpose_split_kernel<<<dim3(Cout / 32, Cin / 32), tb>>>(Wa, wth1, wtl1, Cin, Cout);
    transpose_split_kernel<<<dim3(Cout / 32, Cin / 32), tb>>>(Wb, wth2, wtl2, Cin, Cout);

    dim3 gg(Cout / 128, (n + 127) / 128, 2);
    gemm_mma_kernel<<<gg, 256>>>(x, wth1, wtl1, wth2, wtl2, dinv1, dinv2,
                                 lin1, lin2, n, Cout, Cin);

    int gblocks = (n * 32 + 255) / 256;
    if (Cout == 1024)
        gather_combine_kernel<8><<<gblocks, 256>>>(lin1, lin2, dinv1, dinv2,
                                                   rp1, col1, rp2, col2,
                                                   ba, bb, aw, out, n, Cout);
    else if (Cout == 512)
        gather_combine_kernel<4><<<gblocks, 256>>>(lin1, lin2, dinv1, dinv2,
                                                   rp1, col1, rp2, col2,
                                                   ba, bb, aw, out, n, Cout);
    else
        gather_combine_kernel<1><<<gblocks, 256>>>(lin1, lin2, dinv1, dinv2,
                                                   rp1, col1, rp2, col2,
                                                   ba, bb, aw, out, n, Cout);
}

extern "C" void kernel_launch(void* const* d_in, const int* in_sizes, int n_in,
                              void* d_out, int out_size)
{
    const float* x   = (const float*)d_in[0];
    const int*   ei1 = (const int*)d_in[1];
    const int*   ei2 = (const int*)d_in[2];
    const float* W11 = (const float*)d_in[3];  const float* b11 = (const float*)d_in[4];
    const float* W12 = (const float*)d_in[5];  const float* b12 = (const float*)d_in[6];
    const float* W21 = (const float*)d_in[7];  const float* b21 = (const float*)d_in[8];
    const float* W22 = (const float*)d_in[9];  const float* b22 = (const float*)d_in[10];
    const float* W31 = (const float*)d_in[11]; const float* b31 = (const float*)d_in[12];
    const float* W32 = (const float*)d_in[13]; const float* b32 = (const float*)d_in[14];
    const float* aw1 = (const float*)d_in[15];
    const float* aw2 = (const float*)d_in[16];
    const float* aw3 = (const float*)d_in[17];

    int n  = in_sizes[0] / 512;
    int E1 = in_sizes[1] / 2;
    int E2 = in_sizes[2] / 2;

    const int* src1 = ei1;
    const int* dst1 = ei1 + E1;
    const int* src2 = ei2;
    const int* dst2 = ei2 + E2;

    float *lin1, *lin2, *h, *dinv1, *dinv2;
    int *cnt1, *cnt2, *rp1, *rp2, *cur1, *cur2, *col1, *col2;
    __nv_bfloat16 *wth1, *wtl1, *wth2, *wtl2;
    cudaGetSymbolAddress((void**)&lin1,  g_lin1);
    cudaGetSymbolAddress((void**)&lin2,  g_lin2);
    cudaGetSymbolAddress((void**)&h,     g_h);
    cudaGetSymbolAddress((void**)&dinv1, g_dinv1);
    cudaGetSymbolAddress((void**)&dinv2, g_dinv2);
    cudaGetSymbolAddress((void**)&cnt1,  g_cnt1);
    cudaGetSymbolAddress((void**)&cnt2,  g_cnt2);
    cudaGetSymbolAddress((void**)&rp1,   g_rp1);
    cudaGetSymbolAddress((void**)&rp2,   g_rp2);
    cudaGetSymbolAddress((void**)&cur1,  g_cur1);
    cudaGetSymbolAddress((void**)&cur2,  g_cur2);
    cudaGetSymbolAddress((void**)&col1,  g_col1);
    cudaGetSymbolAddress((void**)&col2,  g_col2);
    cudaGetSymbolAddress((void**)&wth1,  g_wth1);
    cudaGetSymbolAddress((void**)&wtl1,  g_wtl1);
    cudaGetSymbolAddress((void**)&wth2,  g_wth2);
    cudaGetSymbolAddress((void**)&wtl2,  g_wtl2);

    // CSR build
    zero_cnt_kernel<<<(n + 255) / 256, 256>>>(cnt1, cnt2, n);
    count_kernel<<<(E1 + E2 + 255) / 256, 256>>>(dst1, E1, dst2, E2, cnt1, cnt2);
    scan_kernel<<<2, 1024>>>(cnt1, rp1, cur1, dinv1, cnt2, rp2, cur2, dinv2, n);
    fill_kernel<<<(E1 + E2 + 255) / 256, 256>>>(src1, dst1, E1, src2, dst2, E2,
                                                cur1, col1, cur2, col2);

    run_layer(x, n, 512, 1024, W11, b11, W12, b12, aw1,
              lin1, lin2, dinv1, dinv2,
              rp1, col1, rp2, col2, wth1, wtl1, wth2, wtl2, h);

    run_layer(h, n, 1024, 512, W21, b21, W22, b22, aw2,
              lin1, lin2, dinv1, dinv2,
              rp1, col1, rp2, col2, wth1, wtl1, wth2, wtl2, h);

    run_layer(h, n, 512, 128, W31, b31, W32, b32, aw3,
              lin1, lin2, dinv1, dinv2,
              rp1, col1, rp2, col2, wth1, wtl1, wth2, wtl2, (float*)d_out);
}

// round 6
// speedup vs baseline: 3.1786x; 1.1184x over previous
#include <cuda_runtime.h>
#include <cuda_bf16.h>
#include <cstdint>
#include <math.h>

// ===========================================================================
// GCN2 on GB300: double-buffered mma.sync bf16 3-term-split GEMMs
// (fused fp32->bf16 split + dinv row scale, both branches via blockIdx.z)
// + fused dual-CSR gather / bias / ELU / softmax-combine with 4-edge MLP.
// Layers: 512 -> 1024 -> 512 -> 128, N = 10000 nodes, two edge sets.
// ===========================================================================

#define NN 10000
#define CMAX 1024
#define EMAX 200000

__device__ float g_lin1[NN * CMAX];
__device__ float g_lin2[NN * CMAX];
__device__ float g_h   [NN * CMAX];
__device__ float g_dinv1[NN];
__device__ float g_dinv2[NN];
__device__ int   g_cnt1[NN];
__device__ int   g_cnt2[NN];
__device__ int   g_rp1[NN + 1];
__device__ int   g_rp2[NN + 1];
__device__ int   g_cur1[NN];
__device__ int   g_cur2[NN];
__device__ int   g_col1[EMAX];
__device__ int   g_col2[EMAX];
__device__ __nv_bfloat16 g_wth1[1024 * 1024];
__device__ __nv_bfloat16 g_wtl1[1024 * 1024];
__device__ __nv_bfloat16 g_wth2[1024 * 1024];
__device__ __nv_bfloat16 g_wtl2[1024 * 1024];

// ---------------------------------------------------------------------------
__device__ __forceinline__ uint32_t smem_u32(const void* p) {
    uint32_t a;
    asm("{ .reg .u64 t; cvta.to.shared.u64 t, %1; cvt.u32.u64 %0, t; }" : "=r"(a) : "l"(p));
    return a;
}
__device__ __forceinline__ void ldsm_x4(uint32_t r[4], uint32_t addr) {
    asm volatile("ldmatrix.sync.aligned.m8n8.x4.shared.b16 {%0,%1,%2,%3}, [%4];"
                 : "=r"(r[0]), "=r"(r[1]), "=r"(r[2]), "=r"(r[3]) : "r"(addr));
}
__device__ __forceinline__ void mma_bf16(float* c, const uint32_t a[4], const uint32_t* b) {
    asm volatile(
        "mma.sync.aligned.m16n8k16.row.col.f32.bf16.bf16.f32 "
        "{%0,%1,%2,%3}, {%4,%5,%6,%7}, {%8,%9}, {%0,%1,%2,%3};"
        : "+f"(c[0]), "+f"(c[1]), "+f"(c[2]), "+f"(c[3])
        : "r"(a[0]), "r"(a[1]), "r"(a[2]), "r"(a[3]), "r"(b[0]), "r"(b[1]));
}

// ===========================================================================
// CSR build
// ===========================================================================
__global__ void zero_cnt_kernel(int* c1, int* c2, int n) {
    int i = blockIdx.x * blockDim.x + threadIdx.x;
    if (i < n) { c1[i] = 0; c2[i] = 0; }
}
__global__ void count_kernel(const int* __restrict__ dst1, int E1,
                             const int* __restrict__ dst2, int E2,
                             int* c1, int* c2) {
    int i = blockIdx.x * blockDim.x + threadIdx.x;
    if (i < E1) atomicAdd(&c1[dst1[i]], 1);
    else if (i < E1 + E2) atomicAdd(&c2[dst2[i - E1]], 1);
}

__global__ __launch_bounds__(1024) void scan_kernel(
    const int* c1, int* rp1, int* cur1, float* dinv1,
    const int* c2, int* rp2, int* cur2, float* dinv2, int n) {
    __shared__ int buf[1024];
    __shared__ int carry;
    const int* cnt = blockIdx.x ? c2 : c1;
    int* rp   = blockIdx.x ? rp2   : rp1;
    int* cur  = blockIdx.x ? cur2  : cur1;
    float* dv = blockIdx.x ? dinv2 : dinv1;

    int tid = threadIdx.x;
    if (tid == 0) carry = 0;
    __syncthreads();
    for (int base = 0; base < n; base += 1024) {
        int idx = base + tid;
        int x = (idx < n) ? cnt[idx] : 0;
        buf[tid] = x;
        __syncthreads();
        #pragma unroll
        for (int off = 1; off < 1024; off <<= 1) {
            int v = (tid >= off) ? buf[tid - off] : 0;
            __syncthreads();
            buf[tid] += v;
            __syncthreads();
        }
        int excl = buf[tid] - x;
        int c = carry;
        if (idx < n) {
            rp[idx] = c + excl;
            cur[idx] = c + excl;
            dv[idx] = rsqrtf((float)x + 1.0f);
        }
        __syncthreads();
        if (tid == 0) carry = c + buf[1023];
        __syncthreads();
    }
    if (tid == 0) rp[n] = carry;
}

__global__ void fill_kernel(const int* __restrict__ src1, const int* __restrict__ dst1, int E1,
                            const int* __restrict__ src2, const int* __restrict__ dst2, int E2,
                            int* cur1, int* col1, int* cur2, int* col2) {
    int i = blockIdx.x * blockDim.x + threadIdx.x;
    if (i < E1) {
        int pos = atomicAdd(&cur1[dst1[i]], 1);
        col1[pos] = src1[i];
    } else if (i < E1 + E2) {
        int j = i - E1;
        int pos = atomicAdd(&cur2[dst2[j]], 1);
        col2[pos] = src2[j];
    }
}

// ===========================================================================
// Paired weight transpose-split: W[K,N] -> Th/Tl [N,K] (branch via blockIdx.z)
// ===========================================================================
__global__ __launch_bounds__(1024) void transpose_split2_kernel(
    const float* __restrict__ Wa, __nv_bfloat16* __restrict__ Tha, __nv_bfloat16* __restrict__ Tla,
    const float* __restrict__ Wb, __nv_bfloat16* __restrict__ Thb, __nv_bfloat16* __restrict__ Tlb,
    int K, int N) {
    const float* W = blockIdx.z ? Wb : Wa;
    __nv_bfloat16* Th = blockIdx.z ? Thb : Tha;
    __nv_bfloat16* Tl = blockIdx.z ? Tlb : Tla;
    __shared__ float t[32][33];
    int k = blockIdx.y * 32 + threadIdx.y;
    int n = blockIdx.x * 32 + threadIdx.x;
    t[threadIdx.y][threadIdx.x] = W[(size_t)k * N + n];
    __syncthreads();
    int n2 = blockIdx.x * 32 + threadIdx.y;
    int k2 = blockIdx.y * 32 + threadIdx.x;
    float v = t[threadIdx.x][threadIdx.y];
    __nv_bfloat16 h = __float2bfloat16_rn(v);
    Th[(size_t)n2 * K + k2] = h;
    Tl[(size_t)n2 * K + k2] = __float2bfloat16_rn(v - __bfloat162float(h));
}

// ===========================================================================
// GEMM (branches via blockIdx.z): C = ((A@W) * dinv[row])
// A fp32 [M,K] split to bf16 hi/lo in regs; W split [N,K]^T bf16.
// 3-term hh+hl+lh. CTA 128x128, 8 warps 4x2, KC=32, DOUBLE-BUFFERED SMEM
// (one __syncthreads per chunk; next-chunk LDG + STS overlap current MMAs).
// ===========================================================================
#define KC 32
#define LDS 40
#define TILE_B (128 * LDS * 2)      // 10240 B per tile
#define BUFSZ  (4 * TILE_B)         // Ah, Al, Bh, Bl = 40960 B
#define GEMM_SMEM (2 * BUFSZ)       // 81920 B dynamic

__global__ __launch_bounds__(256) void gemm_mma_kernel(
    const float* __restrict__ A,
    const __nv_bfloat16* __restrict__ Bh0, const __nv_bfloat16* __restrict__ Bl0,
    const __nv_bfloat16* __restrict__ Bh1, const __nv_bfloat16* __restrict__ Bl1,
    const float* __restrict__ dinv0, const float* __restrict__ dinv1v,
    float* __restrict__ C0, float* __restrict__ C1,
    int M, int N, int K)
{
    extern __shared__ char smem[];

    const int br = blockIdx.z;
    const __nv_bfloat16* Bh = br ? Bh1 : Bh0;
    const __nv_bfloat16* Bl = br ? Bl1 : Bl0;
    const float* dinv = br ? dinv1v : dinv0;
    float* C = br ? C1 : C0;

    const int tid = threadIdx.x;
    const int warp = tid >> 5;
    const int lane = tid & 31;
    const int wm = warp & 3;
    const int wn = warp >> 2;
    const int m0 = blockIdx.y * 128;
    const int n0 = blockIdx.x * 128;

    const int lr = tid >> 1;
    const int lh = tid & 1;
    const bool valA = (m0 + lr) < M;

    const int li = lane >> 3;
    const int lrow = lane & 7;
    const int a_mr = ((li & 1) << 3) + lrow;
    const int a_kc = (li >> 1) << 3;
    const int b_nr = ((li >> 1) << 3) + lrow;
    const int b_kc = (li & 1) << 3;

    const uint32_t smem_base = smem_u32(smem);
    const uint32_t offA = ((wm * 32 + a_mr) * LDS + a_kc) * 2;
    const uint32_t offB = ((wn * 64 + b_nr) * LDS + b_kc) * 2;
    const uint32_t stO = (lr * LDS + lh * 16) * 2;    // store byte offset in tile

    float acc[2][8][4] = {};

    const float* gA = A + (size_t)(m0 + lr) * K + lh * 16;
    const __nv_bfloat16* gBh = Bh + (size_t)(n0 + lr) * K + lh * 16;
    const __nv_bfloat16* gBl = Bl + (size_t)(n0 + lr) * K + lh * 16;

    float fA[16];
    uint4 rbh[2], rbl[2];

    auto load_g = [&](int kc) {
        if (valA) {
            const float4* p = (const float4*)(gA + kc);
            #pragma unroll
            for (int j = 0; j < 4; j++) {
                float4 v = p[j];
                fA[4 * j + 0] = v.x; fA[4 * j + 1] = v.y;
                fA[4 * j + 2] = v.z; fA[4 * j + 3] = v.w;
            }
        } else {
            #pragma unroll
            for (int j = 0; j < 16; j++) fA[j] = 0.f;
        }
        const uint4* pb = (const uint4*)(gBh + kc);
        rbh[0] = pb[0]; rbh[1] = pb[1];
        pb = (const uint4*)(gBl + kc);
        rbl[0] = pb[0]; rbl[1] = pb[1];
    };

    load_g(0);

    const int nc = K / KC;
    for (int i = 0; i < nc; i++) {
        const uint32_t bb = (i & 1) * BUFSZ;
        char* base = smem + bb;

        // store prefetched chunk i into buf[i&1]
        {
            __nv_bfloat16 hv[16], lv[16];
            #pragma unroll
            for (int j = 0; j < 16; j++) {
                __nv_bfloat16 h = __float2bfloat16_rn(fA[j]);
                hv[j] = h;
                lv[j] = __float2bfloat16_rn(fA[j] - __bfloat162float(h));
            }
            uint4* d;
            d = (uint4*)(base + 0 * TILE_B + stO);
            d[0] = ((uint4*)hv)[0]; d[1] = ((uint4*)hv)[1];
            d = (uint4*)(base + 1 * TILE_B + stO);
            d[0] = ((uint4*)lv)[0]; d[1] = ((uint4*)lv)[1];
            d = (uint4*)(base + 2 * TILE_B + stO);
            d[0] = rbh[0]; d[1] = rbh[1];
            d = (uint4*)(base + 3 * TILE_B + stO);
            d[0] = rbl[0]; d[1] = rbl[1];
        }
        __syncthreads();   // also fences: all warps done with MMAs of chunk i-1

        if (i + 1 < nc) load_g((i + 1) * KC);   // overlaps MMAs below

        const uint32_t sAh_b = smem_base + bb + 0 * TILE_B;
        const uint32_t sAl_b = smem_base + bb + 1 * TILE_B;
        const uint32_t sBh_b = smem_base + bb + 2 * TILE_B;
        const uint32_t sBl_b = smem_base + bb + 3 * TILE_B;

        #pragma unroll
        for (int ks = 0; ks < 2; ks++) {
            const uint32_t kOff = ks * 16 * 2;
            uint32_t ah[2][4], al[2][4];
            #pragma unroll
            for (int mt = 0; mt < 2; mt++) {
                uint32_t o = offA + kOff + mt * (16 * LDS * 2);
                ldsm_x4(ah[mt], sAh_b + o);
                ldsm_x4(al[mt], sAl_b + o);
            }
            uint32_t bh[4][4], bl[4][4];
            #pragma unroll
            for (int p = 0; p < 4; p++) {
                uint32_t o = offB + kOff + p * (16 * LDS * 2);
                ldsm_x4(bh[p], sBh_b + o);
                ldsm_x4(bl[p], sBl_b + o);
            }
            #pragma unroll
            for (int mt = 0; mt < 2; mt++) {
                #pragma unroll
                for (int p = 0; p < 4; p++) {
                    mma_bf16(acc[mt][2 * p],     ah[mt], &bh[p][0]);
                    mma_bf16(acc[mt][2 * p],     ah[mt], &bl[p][0]);
                    mma_bf16(acc[mt][2 * p],     al[mt], &bh[p][0]);
                    mma_bf16(acc[mt][2 * p + 1], ah[mt], &bh[p][2]);
                    mma_bf16(acc[mt][2 * p + 1], ah[mt], &bl[p][2]);
                    mma_bf16(acc[mt][2 * p + 1], al[mt], &bh[p][2]);
                }
            }
        }
        // no trailing sync: next iteration writes the OTHER buffer, and its
        // __syncthreads orders those stores against this chunk's LDSM reads.
    }

    const int r = lane >> 2;
    const int cq = (lane & 3) * 2;
    #pragma unroll
    for (int mt = 0; mt < 2; mt++) {
        int grow = m0 + wm * 32 + mt * 16 + r;
        float dv0 = (grow < M)     ? dinv[grow]     : 0.f;
        float dv1 = (grow + 8 < M) ? dinv[grow + 8] : 0.f;
        #pragma unroll
        for (int nt = 0; nt < 8; nt++) {
            int gcol = n0 + wn * 64 + nt * 8 + cq;
            if (grow < M)
                *(float2*)&C[(size_t)grow * N + gcol] =
                    make_float2(acc[mt][nt][0] * dv0, acc[mt][nt][1] * dv0);
            if (grow + 8 < M)
                *(float2*)&C[(size_t)(grow + 8) * N + gcol] =
                    make_float2(acc[mt][nt][2] * dv1, acc[mt][nt][3] * dv1);
        }
    }
}

// ===========================================================================
// Fused dual gather + bias + ELU + softmax combine.
// Node split across `slices` warps, each covering CPL float4s per lane.
// 4-edge unroll for memory-level parallelism.
// ===========================================================================
__device__ __forceinline__ float elu1(float x) { return x > 0.f ? x : expm1f(x); }

template <int CPL>
__global__ __launch_bounds__(256) void gather_combine_kernel(
    const float* __restrict__ lin1, const float* __restrict__ lin2,
    const float* __restrict__ dinv1, const float* __restrict__ dinv2,
    const int* __restrict__ rp1, const int* __restrict__ col1,
    const int* __restrict__ rp2, const int* __restrict__ col2,
    const float* __restrict__ b1, const float* __restrict__ b2,
    const float* __restrict__ aw,
    float* __restrict__ out, int n, int C, int slices)
{
    int gwarp = (blockIdx.x * blockDim.x + threadIdx.x) >> 5;
    int lane = threadIdx.x & 31;
    int d = gwarp / slices;
    int sl = gwarp - d * slices;
    if (d >= n) return;
    const int f0 = sl * CPL * 32 + lane;   // base float4 index within row

    float4 acc1[CPL], acc2[CPL];
    {
        const float4* s1 = (const float4*)(lin1 + (size_t)d * C);
        const float4* s2 = (const float4*)(lin2 + (size_t)d * C);
        #pragma unroll
        for (int j = 0; j < CPL; j++) { acc1[j] = s1[f0 + j * 32]; acc2[j] = s2[f0 + j * 32]; }
    }

    #pragma unroll
    for (int which = 0; which < 2; which++) {
        const float* lin = which ? lin2 : lin1;
        const int* rp  = which ? rp2  : rp1;
        const int* col = which ? col2 : col1;
        float4* acc = which ? acc2 : acc1;

        int e = rp[d], end = rp[d + 1];
        for (; e + 3 < end; e += 4) {
            const float4* r0 = (const float4*)(lin + (size_t)col[e]     * C);
            const float4* r1 = (const float4*)(lin + (size_t)col[e + 1] * C);
            const float4* r2 = (const float4*)(lin + (size_t)col[e + 2] * C);
            const float4* r3 = (const float4*)(lin + (size_t)col[e + 3] * C);
            #pragma unroll
            for (int j = 0; j < CPL; j++) {
                float4 v0 = r0[f0 + j * 32];
                float4 v1 = r1[f0 + j * 32];
                float4 v2 = r2[f0 + j * 32];
                float4 v3 = r3[f0 + j * 32];
                acc[j].x += (v0.x + v1.x) + (v2.x + v3.x);
                acc[j].y += (v0.y + v1.y) + (v2.y + v3.y);
                acc[j].z += (v0.z + v1.z) + (v2.z + v3.z);
                acc[j].w += (v0.w + v1.w) + (v2.w + v3.w);
            }
        }
        for (; e < end; e++) {
            const float4* r0 = (const float4*)(lin + (size_t)col[e] * C);
            #pragma unroll
            for (int j = 0; j < CPL; j++) {
                float4 v = r0[f0 + j * 32];
                acc[j].x += v.x; acc[j].y += v.y; acc[j].z += v.z; acc[j].w += v.w;
            }
        }
    }

    float dv1 = dinv1[d];
    float dv2 = dinv2[d];
    float4* o = (float4*)(out + (size_t)d * C);
    #pragma unroll
    for (int j = 0; j < CPL; j++) {
        int ci = f0 + j * 32;
        float4 bb1 = ((const float4*)b1)[ci];
        float4 bb2 = ((const float4*)b2)[ci];
        float4 aw0 = ((const float4*)aw)[2 * ci];
        float4 aw1 = ((const float4*)aw)[2 * ci + 1];
        float w0x = 1.0f / (1.0f + expf(aw0.y - aw0.x));
        float w0y = 1.0f / (1.0f + expf(aw0.w - aw0.z));
        float w0z = 1.0f / (1.0f + expf(aw1.y - aw1.x));
        float w0w = 1.0f / (1.0f + expf(aw1.w - aw1.z));
        float4 r;
        r.x = elu1(acc1[j].x * dv1 + bb1.x) * w0x + elu1(acc2[j].x * dv2 + bb2.x) * (1.f - w0x);
        r.y = elu1(acc1[j].y * dv1 + bb1.y) * w0y + elu1(acc2[j].y * dv2 + bb2.y) * (1.f - w0y);
        r.z = elu1(acc1[j].z * dv1 + bb1.z) * w0z + elu1(acc2[j].z * dv2 + bb2.z) * (1.f - w0z);
        r.w = elu1(acc1[j].w * dv1 + bb1.w) * w0w + elu1(acc2[j].w * dv2 + bb2.w) * (1.f - w0w);
        o[ci] = r;
    }
}

// ===========================================================================
// Host
// ===========================================================================
static void run_layer(const float* x, int n, int Cin, int Cout,
                      const float* ba, const float* bb, const float* aw,
                      float* lin1, float* lin2,
                      float* dinv1, float* dinv2,
                      const int* rp1, const int* col1,
                      const int* rp2, const int* col2,
                      __nv_bfloat16* wth1, __nv_bfloat16* wtl1,
                      __nv_bfloat16* wth2, __nv_bfloat16* wtl2,
                      float* out)
{
    dim3 gg(Cout / 128, (n + 127) / 128, 2);
    gemm_mma_kernel<<<gg, 256, GEMM_SMEM>>>(x, wth1, wtl1, wth2, wtl2, dinv1, dinv2,
                                            lin1, lin2, n, Cout, Cin);

    if (Cout == 1024) {
        int slices = 2;
        int gblocks = (n * slices * 32 + 255) / 256;
        gather_combine_kernel<4><<<gblocks, 256>>>(lin1, lin2, dinv1, dinv2,
                                                   rp1, col1, rp2, col2,
                                                   ba, bb, aw, out, n, Cout, slices);
    } else if (Cout == 512) {
        int gblocks = (n * 32 + 255) / 256;
        gather_combine_kernel<4><<<gblocks, 256>>>(lin1, lin2, dinv1, dinv2,
                                                   rp1, col1, rp2, col2,
                                                   ba, bb, aw, out, n, Cout, 1);
    } else {
        int gblocks = (n * 32 + 255) / 256;
        gather_combine_kernel<1><<<gblocks, 256>>>(lin1, lin2, dinv1, dinv2,
                                                   rp1, col1, rp2, col2,
                                                   ba, bb, aw, out, n, Cout, 1);
    }
}

extern "C" void kernel_launch(void* const* d_in, const int* in_sizes, int n_in,
                              void* d_out, int out_size)
{
    const float* x   = (const float*)d_in[0];
    const int*   ei1 = (const int*)d_in[1];
    const int*   ei2 = (const int*)d_in[2];
    const float* W11 = (const float*)d_in[3];  const float* b11 = (const float*)d_in[4];
    const float* W12 = (const float*)d_in[5];  const float* b12 = (const float*)d_in[6];
    const float* W21 = (const float*)d_in[7];  const float* b21 = (const float*)d_in[8];
    const float* W22 = (const float*)d_in[9];  const float* b22 = (const float*)d_in[10];
    const float* W31 = (const float*)d_in[11]; const float* b31 = (const float*)d_in[12];
    const float* W32 = (const float*)d_in[13]; const float* b32 = (const float*)d_in[14];
    const float* aw1 = (const float*)d_in[15];
    const float* aw2 = (const float*)d_in[16];
    const float* aw3 = (const float*)d_in[17];

    int n  = in_sizes[0] / 512;
    int E1 = in_sizes[1] / 2;
    int E2 = in_sizes[2] / 2;

    const int* src1 = ei1;
    const int* dst1 = ei1 + E1;
    const int* src2 = ei2;
    const int* dst2 = ei2 + E2;

    float *lin1, *lin2, *h, *dinv1, *dinv2;
    int *cnt1, *cnt2, *rp1, *rp2, *cur1, *cur2, *col1, *col2;
    __nv_bfloat16 *wth1, *wtl1, *wth2, *wtl2;
    cudaGetSymbolAddress((void**)&lin1,  g_lin1);
    cudaGetSymbolAddress((void**)&lin2,  g_lin2);
    cudaGetSymbolAddress((void**)&h,     g_h);
    cudaGetSymbolAddress((void**)&dinv1, g_dinv1);
    cudaGetSymbolAddress((void**)&dinv2, g_dinv2);
    cudaGetSymbolAddress((void**)&cnt1,  g_cnt1);
    cudaGetSymbolAddress((void**)&cnt2,  g_cnt2);
    cudaGetSymbolAddress((void**)&rp1,   g_rp1);
    cudaGetSymbolAddress((void**)&rp2,   g_rp2);
    cudaGetSymbolAddress((void**)&cur1,  g_cur1);
    cudaGetSymbolAddress((void**)&cur2,  g_cur2);
    cudaGetSymbolAddress((void**)&col1,  g_col1);
    cudaGetSymbolAddress((void**)&col2,  g_col2);
    cudaGetSymbolAddress((void**)&wth1,  g_wth1);
    cudaGetSymbolAddress((void**)&wtl1,  g_wtl1);
    cudaGetSymbolAddress((void**)&wth2,  g_wth2);
    cudaGetSymbolAddress((void**)&wtl2,  g_wtl2);

    cudaFuncSetAttribute(gemm_mma_kernel, cudaFuncAttributeMaxDynamicSharedMemorySize, GEMM_SMEM);

    // CSR build (weights-independent path)
    zero_cnt_kernel<<<(n + 255) / 256, 256>>>(cnt1, cnt2, n);
    count_kernel<<<(E1 + E2 + 255) / 256, 256>>>(dst1, E1, dst2, E2, cnt1, cnt2);
    scan_kernel<<<2, 1024>>>(cnt1, rp1, cur1, dinv1, cnt2, rp2, cur2, dinv2, n);
    fill_kernel<<<(E1 + E2 + 255) / 256, 256>>>(src1, dst1, E1, src2, dst2, E2,
                                                cur1, col1, cur2, col2);

    // Layer 1 (uses wth1..wtl2 as scratch per layer; transpose just-in-time)
    dim3 tb(32, 32);
    transpose_split2_kernel<<<dim3(1024 / 32, 512 / 32, 2), tb>>>(
        W11, wth1, wtl1, W12, wth2, wtl2, 512, 1024);
    run_layer(x, n, 512, 1024, b11, b12, aw1, lin1, lin2, dinv1, dinv2,
              rp1, col1, rp2, col2, wth1, wtl1, wth2, wtl2, h);

    transpose_split2_kernel<<<dim3(512 / 32, 1024 / 32, 2), tb>>>(
        W21, wth1, wtl1, W22, wth2, wtl2, 1024, 512);
    run_layer(h, n, 1024, 512, b21, b22, aw2, lin1, lin2, dinv1, dinv2,
              rp1, col1, rp2, col2, wth1, wtl1, wth2, wtl2, h);

    transpose_split2_kernel<<<dim3(128 / 32, 512 / 32, 2), tb>>>(
        W31, wth1, wtl1, W32, wth2, wtl2, 512, 128);
    run_layer(h, n, 512, 128, b31, b32, aw3, lin1, lin2, dinv1, dinv2,
              rp1, col1, rp2, col2, wth1, wtl1, wth2, wtl2, (float*)d_out);
}